// round 15
// baseline (speedup 1.0000x reference)
#include <cuda_runtime.h>
#include <cuda_bf16.h>
#include <math.h>

using bf16 = __nv_bfloat16;

// ---------------- problem constants ----------------
#define L_TOK 32768
#define C_DIM 256
#define HID_DIM 1024
#define NW 256
#define NH 8
#define T_WIN 128
#define HD 32
#define W_IMG 512
#define EPS 1e-5f
#define SCALE 0.17677669529663687f
#define QKV_N 768

// ---------------- scratch ----------------
static const size_t SZ_LC = (size_t)L_TOK * C_DIM;
__device__ float g_scratch[8 * 8388608ull + (size_t)L_TOK * HID_DIM];
__device__ bf16  g_wbf[786432];   // wqkvT(196608) | woT(65536) | fc1T(262144) | fc2T(262144)
__device__ float g_bqkv[768];

// ---------------- PTX helpers ----------------
__device__ __forceinline__ void cp16(unsigned saddr, const void* g)
{
    asm volatile("cp.async.cg.shared.global [%0], [%1], 16;" :: "r"(saddr), "l"(g));
}
__device__ __forceinline__ void ldsm4(unsigned* r, unsigned addr)
{
    asm volatile("ldmatrix.sync.aligned.m8n8.x4.shared.b16 {%0,%1,%2,%3}, [%4];"
                 : "=r"(r[0]), "=r"(r[1]), "=r"(r[2]), "=r"(r[3]) : "r"(addr));
}
__device__ __forceinline__ void ldsm4t(unsigned* r, unsigned addr)
{
    asm volatile("ldmatrix.sync.aligned.m8n8.x4.trans.shared.b16 {%0,%1,%2,%3}, [%4];"
                 : "=r"(r[0]), "=r"(r[1]), "=r"(r[2]), "=r"(r[3]) : "r"(addr));
}
__device__ __forceinline__ void mma16816(float* d, const unsigned* a, const unsigned* b)
{
    asm volatile("mma.sync.aligned.m16n8k16.row.col.f32.bf16.bf16.f32 "
                 "{%0,%1,%2,%3}, {%4,%5,%6,%7}, {%8,%9}, {%0,%1,%2,%3};"
                 : "+f"(d[0]), "+f"(d[1]), "+f"(d[2]), "+f"(d[3])
                 : "r"(a[0]), "r"(a[1]), "r"(a[2]), "r"(a[3]), "r"(b[0]), "r"(b[1]));
}
__device__ __forceinline__ unsigned packbf(float a, float b)
{
    __nv_bfloat162 h = __floats2bfloat162_rn(a, b);
    return *reinterpret_cast<unsigned*>(&h);
}

// ---------------- merged LN1 + weight pack (both low-register branches) ----------------
// grid: [0,4096) LN rows*8 | [4096,4864) pack
__global__ __launch_bounds__(256)
void lnpack_kernel(const float* __restrict__ x,
                   const float* __restrict__ n1g, const float* __restrict__ n1b,
                   bf16* __restrict__ y,
                   const float* __restrict__ wq, const float* __restrict__ wk,
                   const float* __restrict__ wv, const float* __restrict__ bq,
                   const float* __restrict__ bk, const float* __restrict__ bv,
                   const float* __restrict__ wo, const float* __restrict__ wfc1,
                   const float* __restrict__ wfc2)
{
    const int bid = blockIdx.x;
    const int tid = threadIdx.x;

    if (bid < 4096) {
        const int warp = tid >> 5, lane = tid & 31;
        const long row = (long)bid * 8 + warp;
        const float* xr = x + row * C_DIM + lane * 8;

        const float4 v0 = *reinterpret_cast<const float4*>(xr);
        const float4 v1 = *reinterpret_cast<const float4*>(xr + 4);

        float s  = v0.x + v0.y + v0.z + v0.w + v1.x + v1.y + v1.z + v1.w;
        float sq = v0.x * v0.x + v0.y * v0.y + v0.z * v0.z + v0.w * v0.w
                 + v1.x * v1.x + v1.y * v1.y + v1.z * v1.z + v1.w * v1.w;
        #pragma unroll
        for (int o = 16; o > 0; o >>= 1) {
            s  += __shfl_xor_sync(0xffffffffu, s, o);
            sq += __shfl_xor_sync(0xffffffffu, sq, o);
        }
        const float mean = s * (1.f / 256.f);
        const float var  = sq * (1.f / 256.f) - mean * mean;
        const float inv  = rsqrtf(var + EPS);

        const float4 g0 = *reinterpret_cast<const float4*>(n1g + lane * 8);
        const float4 g1 = *reinterpret_cast<const float4*>(n1g + lane * 8 + 4);
        const float4 b0 = *reinterpret_cast<const float4*>(n1b + lane * 8);
        const float4 b1 = *reinterpret_cast<const float4*>(n1b + lane * 8 + 4);

        uint4 o4;
        o4.x = packbf((v0.x - mean) * inv * g0.x + b0.x, (v0.y - mean) * inv * g0.y + b0.y);
        o4.y = packbf((v0.z - mean) * inv * g0.z + b0.z, (v0.w - mean) * inv * g0.w + b0.w);
        o4.z = packbf((v1.x - mean) * inv * g1.x + b1.x, (v1.y - mean) * inv * g1.y + b1.y);
        o4.w = packbf((v1.z - mean) * inv * g1.z + b1.z, (v1.w - mean) * inv * g1.w + b1.w);
        *reinterpret_cast<uint4*>(y + row * C_DIM + lane * 8) = o4;
    } else {
        const int pb = bid - 4096;                // 0..767
        const int total = 786432 + 768;
        for (int i = pb * 256 + tid; i < total; i += 768 * 256) {
            if (i < 196608) {                     // wqkvT [768][256]
                const int n = i >> 8, k = i & 255;
                float v = (n < 256) ? wq[k * 256 + n] * SCALE
                        : (n < 512) ? wk[k * 256 + n - 256]
                                    : wv[k * 256 + n - 512];
                g_wbf[i] = __float2bfloat16(v);
            } else if (i < 262144) {              // woT [256][256]
                const int j = i - 196608, n = j >> 8, k = j & 255;
                g_wbf[i] = __float2bfloat16(wo[k * 256 + n]);
            } else if (i < 524288) {              // fc1T [1024][256]
                const int j = i - 262144, n = j >> 8, k = j & 255;
                g_wbf[i] = __float2bfloat16(wfc1[k * 1024 + n]);
            } else if (i < 786432) {              // fc2T [256][1024]
                const int j = i - 524288, n = j >> 10, k = j & 1023;
                g_wbf[i] = __float2bfloat16(wfc2[k * 256 + n]);
            } else {
                const int c = i - 786432;
                g_bqkv[c] = (c < 256) ? bq[c] * SCALE
                          : (c < 512) ? bk[c - 256] : bv[c - 512];
            }
        }
    }
}

// ---------------- mma.sync GEMM, 64x128 tile, 128 threads (2x2 warps), 4 CTA/SM ----------------
#define GSTRIDE 72                         // bf16 units per smem row (144B, conflict-free)
#define A_BYTES (64 * GSTRIDE * 2)         // 9216
#define B_BYTES (128 * GSTRIDE * 2)        // 18432
#define STAGE_BYTES (A_BYTES + B_BYTES)    // 27648
#define GEMM_SMEM (2 * STAGE_BYTES + 512)  // 55808

template<int OP, bool BF_OUT>
__global__ __launch_bounds__(128, 4)
void mma_gemm(const bf16* __restrict__ A, const bf16* __restrict__ Bt,
              const float* __restrict__ bias, const float* __restrict__ R,
              void* __restrict__ Cout, int N, int K)
{
    extern __shared__ char smem[];
    const unsigned sb = (unsigned)__cvta_generic_to_shared(smem);
    float* sbias = (float*)(smem + 2 * STAGE_BYTES);

    const int tid  = threadIdx.x;
    const int lane = tid & 31;
    const int wid  = tid >> 5;
    const int wm   = wid >> 1;
    const int wn   = wid & 1;
    const int m0   = blockIdx.y * 64;
    const int n0   = blockIdx.x * 128;

    sbias[tid] = bias[n0 + tid];

    auto issue = [&](int kt, int s) {
        const int kb = kt * 64;
        const unsigned abase = sb + s * STAGE_BYTES;
        const unsigned bbase = abase + A_BYTES;
        #pragma unroll
        for (int p = 0; p < 4; p++) {
            const int id = tid + 128 * p;
            const int r = id >> 3, ch = id & 7;
            cp16(abase + (r * GSTRIDE + ch * 8) * 2, A + (long)(m0 + r) * K + kb + ch * 8);
        }
        #pragma unroll
        for (int p = 0; p < 8; p++) {
            const int id = tid + 128 * p;
            const int r = id >> 3, ch = id & 7;
            cp16(bbase + (r * GSTRIDE + ch * 8) * 2, Bt + (long)(n0 + r) * K + kb + ch * 8);
        }
        asm volatile("cp.async.commit_group;");
    };

    const int mat = lane >> 3, r8 = lane & 7;

    float acc[2][8][4];
    #pragma unroll
    for (int i = 0; i < 2; i++)
        #pragma unroll
        for (int j = 0; j < 8; j++)
            #pragma unroll
            for (int q = 0; q < 4; q++) acc[i][j][q] = 0.f;

    const int KT = K >> 6;
    issue(0, 0);

    for (int kt = 0; kt < KT; kt++) {
        asm volatile("cp.async.wait_group 0;");
        __syncthreads();

        const int s = kt & 1;
        const unsigned abase = sb + s * STAGE_BYTES;
        const unsigned bbase = abase + A_BYTES;

        auto lda = [&](unsigned (*af)[4], int ks) {
            #pragma unroll
            for (int mt = 0; mt < 2; mt++)
                ldsm4(af[mt], abase + ((wm * 32 + mt * 16 + (mat & 1) * 8 + r8) * GSTRIDE
                                       + (mat >> 1) * 8 + ks * 16) * 2);
        };
        auto ldb = [&](unsigned (*bf)[4], int ks) {
            #pragma unroll
            for (int nt = 0; nt < 4; nt++)
                ldsm4(bf[nt], bbase + ((wn * 64 + nt * 16 + (mat >> 1) * 8 + r8) * GSTRIDE
                                       + (mat & 1) * 8 + ks * 16) * 2);
        };

        unsigned af[2][2][4], bf[2][4][4];
        lda(af[0], 0);
        ldb(bf[0], 0);
        if (kt + 1 < KT) issue(kt + 1, s ^ 1);

        #pragma unroll
        for (int ks = 0; ks < 4; ks++) {
            if (ks < 3) {
                lda(af[(ks + 1) & 1], ks + 1);
                ldb(bf[(ks + 1) & 1], ks + 1);
            }
            #pragma unroll
            for (int mt = 0; mt < 2; mt++)
                #pragma unroll
                for (int n8 = 0; n8 < 8; n8++)
                    mma16816(acc[mt][n8], af[ks & 1][mt], &bf[ks & 1][n8 >> 1][(n8 & 1) * 2]);
        }
    }

    const int gr = lane >> 2, tig = lane & 3;
    #pragma unroll
    for (int mt = 0; mt < 2; mt++) {
        #pragma unroll
        for (int n8 = 0; n8 < 8; n8++) {
            const int coll = wn * 64 + n8 * 8 + tig * 2;
            const int col  = n0 + coll;
            const float b0 = sbias[coll], b1 = sbias[coll + 1];
            #pragma unroll
            for (int half = 0; half < 2; half++) {
                const int row = m0 + wm * 32 + mt * 16 + gr + half * 8;
                float v0 = acc[mt][n8][half * 2 + 0] + b0;
                float v1 = acc[mt][n8][half * 2 + 1] + b1;
                if (OP == 1) {
                    const float2 rr = *reinterpret_cast<const float2*>(R + (long)row * N + col);
                    v0 += rr.x; v1 += rr.y;
                }
                if (OP == 2) {
                    v0 = 0.5f * v0 * (1.f + erff(v0 * 0.70710678118654752f));
                    v1 = 0.5f * v1 * (1.f + erff(v1 * 0.70710678118654752f));
                }
                if (BF_OUT) {
                    bf16* C = (bf16*)Cout;
                    *reinterpret_cast<__nv_bfloat162*>(C + (long)row * N + col) =
                        __floats2bfloat162_rn(v0, v1);
                } else {
                    float* C = (float*)Cout;
                    *reinterpret_cast<float2*>(C + (long)row * N + col) = make_float2(v0, v1);
                }
            }
        }
    }
}

// ---------------- fused o-proj + residual + LayerNorm2 (1 sync/chunk pipeline) ----------------
#define WA_BYTES (64 * GSTRIDE * 2)            // 9216
#define WB_BYTES (256 * GSTRIDE * 2)           // 36864
#define WSTAGE (WA_BYTES + WB_BYTES)           // 46080
#define WOLN_SMEM (2 * WSTAGE + 6144)

__global__ __launch_bounds__(256, 2)
void wo_ln_kernel(const bf16* __restrict__ A, const bf16* __restrict__ Bt,
                  const float* __restrict__ bo, const float* __restrict__ x,
                  const float* __restrict__ g2, const float* __restrict__ b2,
                  float* __restrict__ X1, bf16* __restrict__ XN2)
{
    extern __shared__ char smem[];
    const unsigned sb = (unsigned)__cvta_generic_to_shared(smem);
    float* sbo  = (float*)(smem + 2 * WSTAGE);
    float* sg   = sbo + 256;
    float* sb2  = sg + 256;
    float* part = sb2 + 256;     // [64][4]
    float* psq  = part + 256;    // [64][4]
    float* smean = psq + 256;    // [64]
    float* sinv  = smean + 64;   // [64]

    const int tid  = threadIdx.x;
    const int lane = tid & 31;
    const int wid  = tid >> 5;
    const int wm   = wid >> 2;
    const int wn   = wid & 3;
    const int m0   = blockIdx.x * 64;

    sbo[tid] = bo[tid];
    sg[tid]  = g2[tid];
    sb2[tid] = b2[tid];

    auto issue = [&](int kt, int s) {
        const int kb = kt * 64;
        const unsigned abase = sb + s * WSTAGE;
        const unsigned bbase = abase + WA_BYTES;
        #pragma unroll
        for (int p = 0; p < 2; p++) {
            const int id = tid + 256 * p;
            const int r = id >> 3, ch = id & 7;
            cp16(abase + (r * GSTRIDE + ch * 8) * 2, A + (long)(m0 + r) * C_DIM + kb + ch * 8);
        }
        #pragma unroll
        for (int p = 0; p < 8; p++) {
            const int id = tid + 256 * p;
            const int r = id >> 3, ch = id & 7;
            cp16(bbase + (r * GSTRIDE + ch * 8) * 2, Bt + (long)r * C_DIM + kb + ch * 8);
        }
        asm volatile("cp.async.commit_group;");
    };

    const int mat = lane >> 3, r8 = lane & 7;

    float acc[2][8][4];
    #pragma unroll
    for (int i = 0; i < 2; i++)
        #pragma unroll
        for (int j = 0; j < 8; j++)
            #pragma unroll
            for (int q = 0; q < 4; q++) acc[i][j][q] = 0.f;

    issue(0, 0);

    #pragma unroll 1
    for (int kt = 0; kt < 4; kt++) {
        asm volatile("cp.async.wait_group 0;");
        __syncthreads();

        const int s = kt & 1;
        const unsigned abase = sb + s * WSTAGE;
        const unsigned bbase = abase + WA_BYTES;

        auto lda = [&](unsigned (*af)[4], int ks) {
            #pragma unroll
            for (int mt = 0; mt < 2; mt++)
                ldsm4(af[mt], abase + ((wm * 32 + mt * 16 + (mat & 1) * 8 + r8) * GSTRIDE
                                       + (mat >> 1) * 8 + ks * 16) * 2);
        };
        auto ldb = [&](unsigned (*bf)[4], int ks) {
            #pragma unroll
            for (int nt = 0; nt < 4; nt++)
                ldsm4(bf[nt], bbase + ((wn * 64 + nt * 16 + (mat >> 1) * 8 + r8) * GSTRIDE
                                       + (mat & 1) * 8 + ks * 16) * 2);
        };

        unsigned af[2][2][4], bf[2][4][4];
        lda(af[0], 0);
        ldb(bf[0], 0);
        if (kt + 1 < 4) issue(kt + 1, s ^ 1);

        #pragma unroll
        for (int ks = 0; ks < 4; ks++) {
            if (ks < 3) {
                lda(af[(ks + 1) & 1], ks + 1);
                ldb(bf[(ks + 1) & 1], ks + 1);
            }
            #pragma unroll
            for (int mt = 0; mt < 2; mt++)
                #pragma unroll
                for (int n8 = 0; n8 < 8; n8++)
                    mma16816(acc[mt][n8], af[ks & 1][mt], &bf[ks & 1][n8 >> 1][(n8 & 1) * 2]);
        }
    }

    const int gr = lane >> 2, tig = lane & 3;

    #pragma unroll
    for (int mt = 0; mt < 2; mt++) {
        #pragma unroll
        for (int n8 = 0; n8 < 8; n8++) {
            const int col = wn * 64 + n8 * 8 + tig * 2;
            const float c0 = sbo[col], c1 = sbo[col + 1];
            #pragma unroll
            for (int hf = 0; hf < 2; hf++) {
                const long row = m0 + wm * 32 + mt * 16 + gr + hf * 8;
                const float2 rr = *reinterpret_cast<const float2*>(x + row * C_DIM + col);
                acc[mt][n8][hf * 2 + 0] += c0 + rr.x;
                acc[mt][n8][hf * 2 + 1] += c1 + rr.y;
            }
        }
    }

    #pragma unroll
    for (int mt = 0; mt < 2; mt++) {
        #pragma unroll
        for (int hf = 0; hf < 2; hf++) {
            float ls = 0.f, lq = 0.f;
            #pragma unroll
            for (int n8 = 0; n8 < 8; n8++) {
                const float v0 = acc[mt][n8][hf * 2 + 0];
                const float v1 = acc[mt][n8][hf * 2 + 1];
                ls += v0 + v1;
                lq += v0 * v0 + v1 * v1;
            }
            ls += __shfl_xor_sync(0xffffffffu, ls, 1);
            lq += __shfl_xor_sync(0xffffffffu, lq, 1);
            ls += __shfl_xor_sync(0xffffffffu, ls, 2);
            lq += __shfl_xor_sync(0xffffffffu, lq, 2);
            if (tig == 0) {
                const int lr = wm * 32 + mt * 16 + hf * 8 + gr;
                part[lr * 4 + wn] = ls;
                psq[lr * 4 + wn]  = lq;
            }
        }
    }
    __syncthreads();
    if (tid < 64) {
        const float ps = part[tid * 4] + part[tid * 4 + 1] + part[tid * 4 + 2] + part[tid * 4 + 3];
        const float pq = psq[tid * 4]  + psq[tid * 4 + 1]  + psq[tid * 4 + 2]  + psq[tid * 4 + 3];
        const float mean = ps * (1.f / 256.f);
        const float var  = pq * (1.f / 256.f) - mean * mean;
        smean[tid] = mean;
        sinv[tid]  = rsqrtf(var + EPS);
    }
    __syncthreads();

    #pragma unroll
    for (int mt = 0; mt < 2; mt++) {
        #pragma unroll
        for (int hf = 0; hf < 2; hf++) {
            const int lr  = wm * 32 + mt * 16 + hf * 8 + gr;
            const long row = m0 + lr;
            const float mean = smean[lr], inv = sinv[lr];
            #pragma unroll
            for (int n8 = 0; n8 < 8; n8++) {
                const int col = wn * 64 + n8 * 8 + tig * 2;
                const float v0 = acc[mt][n8][hf * 2 + 0];
                const float v1 = acc[mt][n8][hf * 2 + 1];
                *reinterpret_cast<float2*>(X1 + row * C_DIM + col) = make_float2(v0, v1);
                *reinterpret_cast<__nv_bfloat162*>(XN2 + row * C_DIM + col) =
                    __floats2bfloat162_rn((v0 - mean) * inv * sg[col] + sb2[col],
                                          (v1 - mean) * inv * sg[col + 1] + sb2[col + 1]);
            }
        }
    }
}

// ---------------- bias kernel (t-loop split across blockIdx.y) ----------------
__global__ __launch_bounds__(256)
void bias_kernel(const float* __restrict__ pos,
                 const float* __restrict__ pw1, const float* __restrict__ pb1,
                 const float* __restrict__ bn_g, const float* __restrict__ bn_b,
                 const float* __restrict__ bn_m, const float* __restrict__ bn_v,
                 const float* __restrict__ pw2, const float* __restrict__ pb2,
                 bf16* __restrict__ Bias)
{
    __shared__ float sfeat[T_WIN][20];

    const int n    = blockIdx.x;
    const int half = blockIdx.y;
    const int tid  = threadIdx.x;
    const int lane = tid & 31;
    const int warp = tid >> 5;
    const int gr   = lane >> 2;
    const int tig  = lane & 3;
    const int wr   = n >> 4, wc = n & 15;

    if (tid < 128) {
        const int l_t = (wr * 4 + (tid >> 5)) * W_IMG + wc * 32 + (tid & 31);
        const float2 p2 = *reinterpret_cast<const float2*>(pos + (long)l_t * 2);
        #pragma unroll
        for (int i = 0; i < 16; i++) {
            const float sc = bn_g[i] * rsqrtf(bn_v[i] + EPS);
            sfeat[tid][i] = sc * (pw1[2 * i] * p2.x + pw1[2 * i + 1] * p2.y);
        }
    }

    float c0[4];
    const int kk0 = 2 * tig, kk1 = 2 * tig + 1, kk2 = 2 * tig + 8, kk3 = 2 * tig + 9;
    {
        const int ks[4] = {kk0, kk1, kk2, kk3};
        #pragma unroll
        for (int e = 0; e < 4; e++) {
            const int i = ks[e];
            const float sc = bn_g[i] * rsqrtf(bn_v[i] + EPS);
            c0[e] = sc * (pb1[i] - bn_m[i]) + bn_b[i];
        }
    }
    unsigned aw[4];
    aw[0] = packbf(pw2[gr * 16 + kk0], pw2[gr * 16 + kk1]);
    aw[2] = packbf(pw2[gr * 16 + kk2], pw2[gr * 16 + kk3]);
    aw[1] = 0; aw[3] = 0;
    const float pb2g = pb2[gr];
    __syncthreads();

    #pragma unroll 1
    for (int tt = 0; tt < 8; tt++) {
        const int t = warp * 16 + half * 8 + tt;
        const float ct0 = sfeat[t][kk0] + c0[0];
        const float ct1 = sfeat[t][kk1] + c0[1];
        const float ct2 = sfeat[t][kk2] + c0[2];
        const float ct3 = sfeat[t][kk3] + c0[3];
        bf16* orow = Bias + ((long)(gr * NW + n) * T_WIN + t) * T_WIN;

        #pragma unroll
        for (int u0 = 0; u0 < T_WIN; u0 += 8) {
            const int u = u0 + gr;
            const float f0 = fmaxf(ct0 - sfeat[u][kk0], 0.f);
            const float f1 = fmaxf(ct1 - sfeat[u][kk1], 0.f);
            const float f2 = fmaxf(ct2 - sfeat[u][kk2], 0.f);
            const float f3 = fmaxf(ct3 - sfeat[u][kk3], 0.f);
            unsigned bfr[2] = { packbf(f0, f1), packbf(f2, f3) };
            float d[4] = { pb2g, pb2g, 0.f, 0.f };
            mma16816(d, aw, bfr);
            *reinterpret_cast<__nv_bfloat162*>(orow + u0 + 2 * tig) =
                __floats2bfloat162_rn(d[0], d[1]);
        }
    }
}

// ---------------- slim windowed attention ----------------
#define QS_STRIDE 40
#define BS_STRIDE 136

struct AttnSmem {
    bf16 Qs[T_WIN * QS_STRIDE];
    bf16 Ks[T_WIN * QS_STRIDE];
    bf16 Vs[T_WIN * QS_STRIDE];
    bf16 Bs[T_WIN * BS_STRIDE];
};

__global__ __launch_bounds__(256, 2)
void attn_kernel(const bf16* __restrict__ qkv, const bf16* __restrict__ Bias,
                 bf16* __restrict__ O)
{
    extern __shared__ char sraw[];
    AttnSmem& sm = *reinterpret_cast<AttnSmem*>(sraw);

    const int h = blockIdx.x, n = blockIdx.y;
    const int tid = threadIdx.x, lane = tid & 31, warp = tid >> 5;
    const int wr = n >> 4, wc = n & 15;

    const unsigned qb = (unsigned)__cvta_generic_to_shared(sm.Qs);
    const unsigned kb = (unsigned)__cvta_generic_to_shared(sm.Ks);
    const unsigned vb = (unsigned)__cvta_generic_to_shared(sm.Vs);
    const unsigned bb = (unsigned)__cvta_generic_to_shared(sm.Bs);

    {
        const int tok = tid & 127;
        const int l_t = (wr * 4 + (tok >> 5)) * W_IMG + wc * 32 + (tok & 31);
        const bf16* grow = qkv + (long)l_t * QKV_N + h * HD;
        if (tid < 128) {
            #pragma unroll
            for (int c = 0; c < 4; c++)
                cp16(qb + (tok * QS_STRIDE + c * 8) * 2, grow + c * 8);
            cp16(kb + (tok * QS_STRIDE + 0) * 2,  grow + 256);
            cp16(kb + (tok * QS_STRIDE + 8) * 2,  grow + 256 + 8);
        } else {
            cp16(kb + (tok * QS_STRIDE + 16) * 2, grow + 256 + 16);
            cp16(kb + (tok * QS_STRIDE + 24) * 2, grow + 256 + 24);
            #pragma unroll
            for (int c = 0; c < 4; c++)
                cp16(vb + (tok * QS_STRIDE + c * 8) * 2, grow + 512 + c * 8);
        }
        asm volatile("cp.async.commit_group;");
    }

    {
        const int row = tid >> 1, hlf = tid & 1;
        const bf16* brow = Bias + ((long)(h * NW + n) * T_WIN + row) * T_WIN + hlf * 64;
        #pragma unroll
        for (int c = 0; c < 8; c++)
            cp16(bb + (row * BS_STRIDE + hlf * 64 + c * 8) * 2, brow + c * 8);
        asm volatile("cp.async.commit_group;");
    }

    asm volatile("cp.async.wait_group 1;");
    __syncthreads();

    const int mat = lane >> 3, r8 = lane & 7;
    float acc[16][4];
    #pragma unroll
    for (int j = 0; j < 16; j++)
        #pragma unroll
        for (int q = 0; q < 4; q++) acc[j][q] = 0.f;

    #pragma unroll
    for (int ks = 0; ks < 2; ks++) {
        unsigned a[4];
        ldsm4(a, qb + ((warp * 16 + (mat & 1) * 8 + r8) * QS_STRIDE
                       + (mat >> 1) * 8 + ks * 16) * 2);
        #pragma unroll
        for (int nt = 0; nt < 8; nt++) {
            unsigned bfr[4];
            ldsm4(bfr, kb + ((nt * 16 + (mat >> 1) * 8 + r8) * QS_STRIDE
                             + (mat & 1) * 8 + ks * 16) * 2);
            mma16816(acc[2 * nt + 0], a, &bfr[0]);
            mma16816(acc[2 * nt + 1], a, &bfr[2]);
        }
    }

    asm volatile("cp.async.wait_group 0;");
    __syncthreads();

    const int gr = lane >> 2, tig = lane & 3;
    float inv2[2];
    #pragma unroll
    for (int hf = 0; hf < 2; hf++) {
        const int row = warp * 16 + gr + hf * 8;
        float m = -1e30f;
        #pragma unroll
        for (int j = 0; j < 16; j++) {
            const __nv_bfloat162 bb2 = *reinterpret_cast<const __nv_bfloat162*>(
                &sm.Bs[row * BS_STRIDE + j * 8 + tig * 2]);
            const float2 bf = __bfloat1622float2(bb2);
            const float v0 = acc[j][hf * 2 + 0] + bf.x;
            const float v1 = acc[j][hf * 2 + 1] + bf.y;
            acc[j][hf * 2 + 0] = v0;
            acc[j][hf * 2 + 1] = v1;
            m = fmaxf(m, fmaxf(v0, v1));
        }
        m = fmaxf(m, __shfl_xor_sync(0xffffffffu, m, 1));
        m = fmaxf(m, __shfl_xor_sync(0xffffffffu, m, 2));
        float rs = 0.f;
        #pragma unroll
        for (int j = 0; j < 16; j++) {
            const float p0 = __expf(acc[j][hf * 2 + 0] - m);
            const float p1 = __expf(acc[j][hf * 2 + 1] - m);
            acc[j][hf * 2 + 0] = p0;
            acc[j][hf * 2 + 1] = p1;
            rs += p0 + p1;
        }
        rs += __shfl_xor_sync(0xffffffffu, rs, 1);
        rs += __shfl_xor_sync(0xffffffffu, rs, 2);
        inv2[hf] = 1.f / rs;
    }

    float oacc[4][4];
    #pragma unroll
    for (int j = 0; j < 4; j++)
        #pragma unroll
        for (int q = 0; q < 4; q++) oacc[j][q] = 0.f;

    #pragma unroll
    for (int kk = 0; kk < 8; kk++) {
        unsigned ap[4];
        ap[0] = packbf(acc[2 * kk][0],     acc[2 * kk][1]);
        ap[1] = packbf(acc[2 * kk][2],     acc[2 * kk][3]);
        ap[2] = packbf(acc[2 * kk + 1][0], acc[2 * kk + 1][1]);
        ap[3] = packbf(acc[2 * kk + 1][2], acc[2 * kk + 1][3]);
        #pragma unroll
        for (int vt = 0; vt < 2; vt++) {
            unsigned bv4[4];
            ldsm4t(bv4, vb + ((kk * 16 + (mat & 1) * 8 + r8) * QS_STRIDE
                              + (mat >> 1) * 8 + vt * 16) * 2);
            mma16816(oacc[2 * vt + 0], ap, &bv4[0]);
            mma16816(oacc[2 * vt + 1], ap, &bv4[2]);
        }
    }

    #pragma unroll
    for (int hf = 0; hf < 2; hf++) {
        const int row  = warp * 16 + gr + hf * 8;
        const int lrow = (wr * 4 + (row >> 5)) * W_IMG + wc * 32 + (row & 31);
        bf16* orow = O + (long)lrow * C_DIM + h * HD;
        const float sc = inv2[hf];
        #pragma unroll
        for (int j = 0; j < 4; j++) {
            *reinterpret_cast<__nv_bfloat162*>(orow + j * 8 + tig * 2) =
                __floats2bfloat162_rn(oacc[j][hf * 2 + 0] * sc,
                                      oacc[j][hf * 2 + 1] * sc);
        }
    }
}

// ---------------- launch ----------------
extern "C" void kernel_launch(void* const* d_in, const int* in_sizes, int n_in,
                              void* d_out, int out_size)
{
    const float* x      = (const float*)d_in[0];
    const float* pos    = (const float*)d_in[1];
    const float* n1g    = (const float*)d_in[2];
    const float* n1b    = (const float*)d_in[3];
    const float* wq     = (const float*)d_in[4];
    const float* bq     = (const float*)d_in[5];
    const float* wk     = (const float*)d_in[6];
    const float* bk     = (const float*)d_in[7];
    const float* wv     = (const float*)d_in[8];
    const float* bv     = (const float*)d_in[9];
    const float* wo     = (const float*)d_in[10];
    const float* bo     = (const float*)d_in[11];
    const float* n2g    = (const float*)d_in[12];
    const float* n2b    = (const float*)d_in[13];
    const float* wfc1   = (const float*)d_in[14];
    const float* bfc1   = (const float*)d_in[15];
    const float* wfc2   = (const float*)d_in[16];
    const float* bfc2   = (const float*)d_in[17];
    const float* pw1    = (const float*)d_in[18];
    const float* pb1    = (const float*)d_in[19];
    const float* bn_g   = (const float*)d_in[20];
    const float* bn_b   = (const float*)d_in[21];
    const float* bn_m   = (const float*)d_in[22];
    const float* bn_v   = (const float*)d_in[23];
    const float* pw2    = (const float*)d_in[24];
    const float* pb2    = (const float*)d_in[25];
    float* out = (float*)d_out;

    float* base = nullptr;
    cudaGetSymbolAddress((void**)&base, g_scratch);
    bf16*  xn   = (bf16*)(base + 0 * SZ_LC);
    bf16*  qkv  = (bf16*)(base + 1 * SZ_LC);     // slots 1-2
    bf16*  o    = (bf16*)(base + 3 * SZ_LC);
    float* x1   = base + 4 * SZ_LC;
    bf16*  xn2  = (bf16*)(base + 5 * SZ_LC);
    bf16*  hid  = (bf16*)(base + 6 * SZ_LC);     // slots 6-7
    bf16*  Bias = (bf16*)(base + 8 * SZ_LC);     // 64MB tail region

    bf16* wbf = nullptr;
    cudaGetSymbolAddress((void**)&wbf, g_wbf);
    bf16* wqkv_t = wbf + 0;
    bf16* wo_t   = wbf + 196608;
    bf16* fc1_t  = wbf + 262144;
    bf16* fc2_t  = wbf + 524288;
    float* bqkv = nullptr;
    cudaGetSymbolAddress((void**)&bqkv, g_bqkv);

    cudaFuncSetAttribute(mma_gemm<0, true>,  cudaFuncAttributeMaxDynamicSharedMemorySize, GEMM_SMEM);
    cudaFuncSetAttribute(mma_gemm<2, true>,  cudaFuncAttributeMaxDynamicSharedMemorySize, GEMM_SMEM);
    cudaFuncSetAttribute(mma_gemm<1, false>, cudaFuncAttributeMaxDynamicSharedMemorySize, GEMM_SMEM);
    cudaFuncSetAttribute(wo_ln_kernel, cudaFuncAttributeMaxDynamicSharedMemorySize, WOLN_SMEM);
    cudaFuncSetAttribute(attn_kernel, cudaFuncAttributeMaxDynamicSharedMemorySize, (int)sizeof(AttnSmem));

    // 0. merged LN1 + weight pack, then bias tensor
    lnpack_kernel<<<4096 + 768, 256>>>(x, n1g, n1b, xn,
                                       wq, wk, wv, bq, bk, bv, wo, wfc1, wfc2);
    bias_kernel<<<dim3(NW, 2), 256>>>(pos, pw1, pb1, bn_g, bn_b, bn_m, bn_v, pw2, pb2, Bias);

    // 1. qkv = xn @ wqkvT^T + bqkv   (q pre-scaled)
    mma_gemm<0, true><<<dim3(QKV_N / 128, L_TOK / 64), 128, GEMM_SMEM>>>(
        xn, wqkv_t, bqkv, nullptr, qkv, QKV_N, C_DIM);

    // 2. attention
    attn_kernel<<<dim3(NH, NW), 256, sizeof(AttnSmem)>>>(qkv, Bias, o);

    // 3. fused: x1 = x + o @ woT^T + bo ; xn2 = LN2(x1)
    wo_ln_kernel<<<L_TOK / 64, 256, WOLN_SMEM>>>(o, wo_t, bo, x, n2g, n2b, x1, xn2);

    // 4. hid = gelu(xn2 @ fc1T^T + bfc1)
    mma_gemm<2, true><<<dim3(HID_DIM / 128, L_TOK / 64), 128, GEMM_SMEM>>>(
        xn2, fc1_t, bfc1, nullptr, hid, HID_DIM, C_DIM);

    // 5. out = x1 + hid @ fc2T^T + bfc2
    mma_gemm<1, false><<<dim3(C_DIM / 128, L_TOK / 64), 128, GEMM_SMEM>>>(
        hid, fc2_t, bfc2, x1, out, C_DIM, HID_DIM);
}

// round 16
// speedup vs baseline: 1.0014x; 1.0014x over previous
#include <cuda_runtime.h>
#include <cuda_bf16.h>
#include <math.h>

using bf16 = __nv_bfloat16;

// ---------------- problem constants ----------------
#define L_TOK 32768
#define C_DIM 256
#define HID_DIM 1024
#define NW 256
#define NH 8
#define T_WIN 128
#define HD 32
#define W_IMG 512
#define EPS 1e-5f
#define SCALE 0.17677669529663687f
#define QKV_N 768

// ---------------- scratch ----------------
static const size_t SZ_LC = (size_t)L_TOK * C_DIM;
__device__ float g_scratch[8 * 8388608ull + (size_t)L_TOK * HID_DIM];
__device__ bf16  g_wbf[786432];   // wqkvT(196608) | woT(65536) | fc1T(262144) | fc2T(262144)
__device__ float g_bqkv[768];

// ---------------- PTX helpers ----------------
__device__ __forceinline__ void cp16(unsigned saddr, const void* g)
{
    asm volatile("cp.async.cg.shared.global [%0], [%1], 16;" :: "r"(saddr), "l"(g));
}
__device__ __forceinline__ void ldsm4(unsigned* r, unsigned addr)
{
    asm volatile("ldmatrix.sync.aligned.m8n8.x4.shared.b16 {%0,%1,%2,%3}, [%4];"
                 : "=r"(r[0]), "=r"(r[1]), "=r"(r[2]), "=r"(r[3]) : "r"(addr));
}
__device__ __forceinline__ void ldsm4t(unsigned* r, unsigned addr)
{
    asm volatile("ldmatrix.sync.aligned.m8n8.x4.trans.shared.b16 {%0,%1,%2,%3}, [%4];"
                 : "=r"(r[0]), "=r"(r[1]), "=r"(r[2]), "=r"(r[3]) : "r"(addr));
}
__device__ __forceinline__ void mma16816(float* d, const unsigned* a, const unsigned* b)
{
    asm volatile("mma.sync.aligned.m16n8k16.row.col.f32.bf16.bf16.f32 "
                 "{%0,%1,%2,%3}, {%4,%5,%6,%7}, {%8,%9}, {%0,%1,%2,%3};"
                 : "+f"(d[0]), "+f"(d[1]), "+f"(d[2]), "+f"(d[3])
                 : "r"(a[0]), "r"(a[1]), "r"(a[2]), "r"(a[3]), "r"(b[0]), "r"(b[1]));
}
__device__ __forceinline__ unsigned packbf(float a, float b)
{
    __nv_bfloat162 h = __floats2bfloat162_rn(a, b);
    return *reinterpret_cast<unsigned*>(&h);
}

// ---------------- pack: bf16 + transpose weights to [N,K] K-major ----------------
__global__ void pack_kernel(const float* __restrict__ wq, const float* __restrict__ wk,
                            const float* __restrict__ wv, const float* __restrict__ bq,
                            const float* __restrict__ bk, const float* __restrict__ bv,
                            const float* __restrict__ wo, const float* __restrict__ wfc1,
                            const float* __restrict__ wfc2)
{
    const int total = 786432 + 768;
    for (int i = blockIdx.x * blockDim.x + threadIdx.x; i < total; i += gridDim.x * blockDim.x) {
        if (i < 196608) {                         // wqkvT [768][256]
            const int n = i >> 8, k = i & 255;
            float v = (n < 256) ? wq[k * 256 + n] * SCALE
                    : (n < 512) ? wk[k * 256 + n - 256]
                                : wv[k * 256 + n - 512];
            g_wbf[i] = __float2bfloat16(v);
        } else if (i < 262144) {                  // woT [256][256]
            const int j = i - 196608, n = j >> 8, k = j & 255;
            g_wbf[i] = __float2bfloat16(wo[k * 256 + n]);
        } else if (i < 524288) {                  // fc1T [1024][256]
            const int j = i - 262144, n = j >> 8, k = j & 255;
            g_wbf[i] = __float2bfloat16(wfc1[k * 1024 + n]);
        } else if (i < 786432) {                  // fc2T [256][1024]
            const int j = i - 524288, n = j >> 10, k = j & 1023;
            g_wbf[i] = __float2bfloat16(wfc2[k * 256 + n]);
        } else {
            const int c = i - 786432;
            g_bqkv[c] = (c < 256) ? bq[c] * SCALE : (c < 512) ? bk[c - 256] : bv[c - 512];
        }
    }
}

// ---------------- LayerNorm: warp per row, float4x2 per lane ----------------
__global__ __launch_bounds__(256)
void ln_kernel(const float* __restrict__ x,
               const float* __restrict__ g,
               const float* __restrict__ b,
               bf16* __restrict__ y)
{
    const int warp = threadIdx.x >> 5, lane = threadIdx.x & 31;
    const long row = (long)blockIdx.x * 8 + warp;
    const float* xr = x + row * C_DIM + lane * 8;

    const float4 v0 = *reinterpret_cast<const float4*>(xr);
    const float4 v1 = *reinterpret_cast<const float4*>(xr + 4);

    float s  = v0.x + v0.y + v0.z + v0.w + v1.x + v1.y + v1.z + v1.w;
    float sq = v0.x * v0.x + v0.y * v0.y + v0.z * v0.z + v0.w * v0.w
             + v1.x * v1.x + v1.y * v1.y + v1.z * v1.z + v1.w * v1.w;
    #pragma unroll
    for (int o = 16; o > 0; o >>= 1) {
        s  += __shfl_xor_sync(0xffffffffu, s, o);
        sq += __shfl_xor_sync(0xffffffffu, sq, o);
    }
    const float mean = s * (1.f / 256.f);
    const float var  = sq * (1.f / 256.f) - mean * mean;
    const float inv  = rsqrtf(var + EPS);

    const float4 g0 = *reinterpret_cast<const float4*>(g + lane * 8);
    const float4 g1 = *reinterpret_cast<const float4*>(g + lane * 8 + 4);
    const float4 b0 = *reinterpret_cast<const float4*>(b + lane * 8);
    const float4 b1 = *reinterpret_cast<const float4*>(b + lane * 8 + 4);

    uint4 o4;
    o4.x = packbf((v0.x - mean) * inv * g0.x + b0.x, (v0.y - mean) * inv * g0.y + b0.y);
    o4.y = packbf((v0.z - mean) * inv * g0.z + b0.z, (v0.w - mean) * inv * g0.w + b0.w);
    o4.z = packbf((v1.x - mean) * inv * g1.x + b1.x, (v1.y - mean) * inv * g1.y + b1.y);
    o4.w = packbf((v1.z - mean) * inv * g1.z + b1.z, (v1.w - mean) * inv * g1.w + b1.w);
    *reinterpret_cast<uint4*>(y + row * C_DIM + lane * 8) = o4;
}

// ---------------- mma.sync GEMM, 64x128 tile, 128 threads (2x2 warps), 4 CTA/SM ----------------
#define GSTRIDE 72                         // bf16 units per smem row (144B, conflict-free)
#define A_BYTES (64 * GSTRIDE * 2)         // 9216
#define B_BYTES (128 * GSTRIDE * 2)        // 18432
#define STAGE_BYTES (A_BYTES + B_BYTES)    // 27648
#define GEMM_SMEM (2 * STAGE_BYTES + 512)  // 55808

template<int OP, bool BF_OUT>
__global__ __launch_bounds__(128, 4)
void mma_gemm(const bf16* __restrict__ A, const bf16* __restrict__ Bt,
              const float* __restrict__ bias, const float* __restrict__ R,
              void* __restrict__ Cout, int N, int K)
{
    extern __shared__ char smem[];
    const unsigned sb = (unsigned)__cvta_generic_to_shared(smem);
    float* sbias = (float*)(smem + 2 * STAGE_BYTES);

    const int tid  = threadIdx.x;
    const int lane = tid & 31;
    const int wid  = tid >> 5;
    const int wm   = wid >> 1;
    const int wn   = wid & 1;
    const int m0   = blockIdx.y * 64;
    const int n0   = blockIdx.x * 128;

    sbias[tid] = bias[n0 + tid];

    auto issue = [&](int kt, int s) {
        const int kb = kt * 64;
        const unsigned abase = sb + s * STAGE_BYTES;
        const unsigned bbase = abase + A_BYTES;
        #pragma unroll
        for (int p = 0; p < 4; p++) {
            const int id = tid + 128 * p;
            const int r = id >> 3, ch = id & 7;
            cp16(abase + (r * GSTRIDE + ch * 8) * 2, A + (long)(m0 + r) * K + kb + ch * 8);
        }
        #pragma unroll
        for (int p = 0; p < 8; p++) {
            const int id = tid + 128 * p;
            const int r = id >> 3, ch = id & 7;
            cp16(bbase + (r * GSTRIDE + ch * 8) * 2, Bt + (long)(n0 + r) * K + kb + ch * 8);
        }
        asm volatile("cp.async.commit_group;");
    };

    const int mat = lane >> 3, r8 = lane & 7;

    float acc[2][8][4];
    #pragma unroll
    for (int i = 0; i < 2; i++)
        #pragma unroll
        for (int j = 0; j < 8; j++)
            #pragma unroll
            for (int q = 0; q < 4; q++) acc[i][j][q] = 0.f;

    const int KT = K >> 6;
    issue(0, 0);

    for (int kt = 0; kt < KT; kt++) {
        asm volatile("cp.async.wait_group 0;");
        __syncthreads();

        const int s = kt & 1;
        const unsigned abase = sb + s * STAGE_BYTES;
        const unsigned bbase = abase + A_BYTES;

        auto lda = [&](unsigned (*af)[4], int ks) {
            #pragma unroll
            for (int mt = 0; mt < 2; mt++)
                ldsm4(af[mt], abase + ((wm * 32 + mt * 16 + (mat & 1) * 8 + r8) * GSTRIDE
                                       + (mat >> 1) * 8 + ks * 16) * 2);
        };
        auto ldb = [&](unsigned (*bf)[4], int ks) {
            #pragma unroll
            for (int nt = 0; nt < 4; nt++)
                ldsm4(bf[nt], bbase + ((wn * 64 + nt * 16 + (mat >> 1) * 8 + r8) * GSTRIDE
                                       + (mat & 1) * 8 + ks * 16) * 2);
        };

        unsigned af[2][2][4], bf[2][4][4];
        lda(af[0], 0);
        ldb(bf[0], 0);
        if (kt + 1 < KT) issue(kt + 1, s ^ 1);

        #pragma unroll
        for (int ks = 0; ks < 4; ks++) {
            if (ks < 3) {
                lda(af[(ks + 1) & 1], ks + 1);
                ldb(bf[(ks + 1) & 1], ks + 1);
            }
            #pragma unroll
            for (int mt = 0; mt < 2; mt++)
                #pragma unroll
                for (int n8 = 0; n8 < 8; n8++)
                    mma16816(acc[mt][n8], af[ks & 1][mt], &bf[ks & 1][n8 >> 1][(n8 & 1) * 2]);
        }
    }

    const int gr = lane >> 2, tig = lane & 3;
    #pragma unroll
    for (int mt = 0; mt < 2; mt++) {
        #pragma unroll
        for (int n8 = 0; n8 < 8; n8++) {
            const int coll = wn * 64 + n8 * 8 + tig * 2;
            const int col  = n0 + coll;
            const float b0 = sbias[coll], b1 = sbias[coll + 1];
            #pragma unroll
            for (int half = 0; half < 2; half++) {
                const int row = m0 + wm * 32 + mt * 16 + gr + half * 8;
                float v0 = acc[mt][n8][half * 2 + 0] + b0;
                float v1 = acc[mt][n8][half * 2 + 1] + b1;
                if (OP == 1) {
                    const float2 rr = *reinterpret_cast<const float2*>(R + (long)row * N + col);
                    v0 += rr.x; v1 += rr.y;
                }
                if (OP == 2) {
                    v0 = 0.5f * v0 * (1.f + erff(v0 * 0.70710678118654752f));
                    v1 = 0.5f * v1 * (1.f + erff(v1 * 0.70710678118654752f));
                }
                if (BF_OUT) {
                    bf16* C = (bf16*)Cout;
                    *reinterpret_cast<__nv_bfloat162*>(C + (long)row * N + col) =
                        __floats2bfloat162_rn(v0, v1);
                } else {
                    float* C = (float*)Cout;
                    *reinterpret_cast<float2*>(C + (long)row * N + col) = make_float2(v0, v1);
                }
            }
        }
    }
}

// ---------------- fused o-proj + residual + LayerNorm2 (1 sync/chunk pipeline) ----------------
#define WA_BYTES (64 * GSTRIDE * 2)            // 9216
#define WB_BYTES (256 * GSTRIDE * 2)           // 36864
#define WSTAGE (WA_BYTES + WB_BYTES)           // 46080
#define WOLN_SMEM (2 * WSTAGE + 6144)

__global__ __launch_bounds__(256, 2)
void wo_ln_kernel(const bf16* __restrict__ A, const bf16* __restrict__ Bt,
                  const float* __restrict__ bo, const float* __restrict__ x,
                  const float* __restrict__ g2, const float* __restrict__ b2,
                  float* __restrict__ X1, bf16* __restrict__ XN2)
{
    extern __shared__ char smem[];
    const unsigned sb = (unsigned)__cvta_generic_to_shared(smem);
    float* sbo  = (float*)(smem + 2 * WSTAGE);
    float* sg   = sbo + 256;
    float* sb2  = sg + 256;
    float* part = sb2 + 256;     // [64][4]
    float* psq  = part + 256;    // [64][4]
    float* smean = psq + 256;    // [64]
    float* sinv  = smean + 64;   // [64]

    const int tid  = threadIdx.x;
    const int lane = tid & 31;
    const int wid  = tid >> 5;
    const int wm   = wid >> 2;
    const int wn   = wid & 3;
    const int m0   = blockIdx.x * 64;

    sbo[tid] = bo[tid];
    sg[tid]  = g2[tid];
    sb2[tid] = b2[tid];

    auto issue = [&](int kt, int s) {
        const int kb = kt * 64;
        const unsigned abase = sb + s * WSTAGE;
        const unsigned bbase = abase + WA_BYTES;
        #pragma unroll
        for (int p = 0; p < 2; p++) {
            const int id = tid + 256 * p;
            const int r = id >> 3, ch = id & 7;
            cp16(abase + (r * GSTRIDE + ch * 8) * 2, A + (long)(m0 + r) * C_DIM + kb + ch * 8);
        }
        #pragma unroll
        for (int p = 0; p < 8; p++) {
            const int id = tid + 256 * p;
            const int r = id >> 3, ch = id & 7;
            cp16(bbase + (r * GSTRIDE + ch * 8) * 2, Bt + (long)r * C_DIM + kb + ch * 8);
        }
        asm volatile("cp.async.commit_group;");
    };

    const int mat = lane >> 3, r8 = lane & 7;

    float acc[2][8][4];
    #pragma unroll
    for (int i = 0; i < 2; i++)
        #pragma unroll
        for (int j = 0; j < 8; j++)
            #pragma unroll
            for (int q = 0; q < 4; q++) acc[i][j][q] = 0.f;

    issue(0, 0);

    #pragma unroll 1
    for (int kt = 0; kt < 4; kt++) {
        asm volatile("cp.async.wait_group 0;");
        __syncthreads();

        const int s = kt & 1;
        const unsigned abase = sb + s * WSTAGE;
        const unsigned bbase = abase + WA_BYTES;

        auto lda = [&](unsigned (*af)[4], int ks) {
            #pragma unroll
            for (int mt = 0; mt < 2; mt++)
                ldsm4(af[mt], abase + ((wm * 32 + mt * 16 + (mat & 1) * 8 + r8) * GSTRIDE
                                       + (mat >> 1) * 8 + ks * 16) * 2);
        };
        auto ldb = [&](unsigned (*bf)[4], int ks) {
            #pragma unroll
            for (int nt = 0; nt < 4; nt++)
                ldsm4(bf[nt], bbase + ((wn * 64 + nt * 16 + (mat >> 1) * 8 + r8) * GSTRIDE
                                       + (mat & 1) * 8 + ks * 16) * 2);
        };

        unsigned af[2][2][4], bf[2][4][4];
        lda(af[0], 0);
        ldb(bf[0], 0);
        if (kt + 1 < 4) issue(kt + 1, s ^ 1);

        #pragma unroll
        for (int ks = 0; ks < 4; ks++) {
            if (ks < 3) {
                lda(af[(ks + 1) & 1], ks + 1);
                ldb(bf[(ks + 1) & 1], ks + 1);
            }
            #pragma unroll
            for (int mt = 0; mt < 2; mt++)
                #pragma unroll
                for (int n8 = 0; n8 < 8; n8++)
                    mma16816(acc[mt][n8], af[ks & 1][mt], &bf[ks & 1][n8 >> 1][(n8 & 1) * 2]);
        }
    }

    const int gr = lane >> 2, tig = lane & 3;

    #pragma unroll
    for (int mt = 0; mt < 2; mt++) {
        #pragma unroll
        for (int n8 = 0; n8 < 8; n8++) {
            const int col = wn * 64 + n8 * 8 + tig * 2;
            const float c0 = sbo[col], c1 = sbo[col + 1];
            #pragma unroll
            for (int hf = 0; hf < 2; hf++) {
                const long row = m0 + wm * 32 + mt * 16 + gr + hf * 8;
                const float2 rr = *reinterpret_cast<const float2*>(x + row * C_DIM + col);
                acc[mt][n8][hf * 2 + 0] += c0 + rr.x;
                acc[mt][n8][hf * 2 + 1] += c1 + rr.y;
            }
        }
    }

    #pragma unroll
    for (int mt = 0; mt < 2; mt++) {
        #pragma unroll
        for (int hf = 0; hf < 2; hf++) {
            float ls = 0.f, lq = 0.f;
            #pragma unroll
            for (int n8 = 0; n8 < 8; n8++) {
                const float v0 = acc[mt][n8][hf * 2 + 0];
                const float v1 = acc[mt][n8][hf * 2 + 1];
                ls += v0 + v1;
                lq += v0 * v0 + v1 * v1;
            }
            ls += __shfl_xor_sync(0xffffffffu, ls, 1);
            lq += __shfl_xor_sync(0xffffffffu, lq, 1);
            ls += __shfl_xor_sync(0xffffffffu, ls, 2);
            lq += __shfl_xor_sync(0xffffffffu, lq, 2);
            if (tig == 0) {
                const int lr = wm * 32 + mt * 16 + hf * 8 + gr;
                part[lr * 4 + wn] = ls;
                psq[lr * 4 + wn]  = lq;
            }
        }
    }
    __syncthreads();
    if (tid < 64) {
        const float ps = part[tid * 4] + part[tid * 4 + 1] + part[tid * 4 + 2] + part[tid * 4 + 3];
        const float pq = psq[tid * 4]  + psq[tid * 4 + 1]  + psq[tid * 4 + 2]  + psq[tid * 4 + 3];
        const float mean = ps * (1.f / 256.f);
        const float var  = pq * (1.f / 256.f) - mean * mean;
        smean[tid] = mean;
        sinv[tid]  = rsqrtf(var + EPS);
    }
    __syncthreads();

    #pragma unroll
    for (int mt = 0; mt < 2; mt++) {
        #pragma unroll
        for (int hf = 0; hf < 2; hf++) {
            const int lr  = wm * 32 + mt * 16 + hf * 8 + gr;
            const long row = m0 + lr;
            const float mean = smean[lr], inv = sinv[lr];
            #pragma unroll
            for (int n8 = 0; n8 < 8; n8++) {
                const int col = wn * 64 + n8 * 8 + tig * 2;
                const float v0 = acc[mt][n8][hf * 2 + 0];
                const float v1 = acc[mt][n8][hf * 2 + 1];
                *reinterpret_cast<float2*>(X1 + row * C_DIM + col) = make_float2(v0, v1);
                *reinterpret_cast<__nv_bfloat162*>(XN2 + row * C_DIM + col) =
                    __floats2bfloat162_rn((v0 - mean) * inv * sg[col] + sb2[col],
                                          (v1 - mean) * inv * sg[col + 1] + sb2[col + 1]);
            }
        }
    }
}

// ---------------- bias kernel (t-loop split across blockIdx.y) ----------------
__global__ __launch_bounds__(256)
void bias_kernel(const float* __restrict__ pos,
                 const float* __restrict__ pw1, const float* __restrict__ pb1,
                 const float* __restrict__ bn_g, const float* __restrict__ bn_b,
                 const float* __restrict__ bn_m, const float* __restrict__ bn_v,
                 const float* __restrict__ pw2, const float* __restrict__ pb2,
                 bf16* __restrict__ Bias)
{
    __shared__ float sfeat[T_WIN][20];

    const int n    = blockIdx.x;
    const int half = blockIdx.y;
    const int tid  = threadIdx.x;
    const int lane = tid & 31;
    const int warp = tid >> 5;
    const int gr   = lane >> 2;
    const int tig  = lane & 3;
    const int wr   = n >> 4, wc = n & 15;

    if (tid < 128) {
        const int l_t = (wr * 4 + (tid >> 5)) * W_IMG + wc * 32 + (tid & 31);
        const float2 p2 = *reinterpret_cast<const float2*>(pos + (long)l_t * 2);
        #pragma unroll
        for (int i = 0; i < 16; i++) {
            const float sc = bn_g[i] * rsqrtf(bn_v[i] + EPS);
            sfeat[tid][i] = sc * (pw1[2 * i] * p2.x + pw1[2 * i + 1] * p2.y);
        }
    }

    float c0[4];
    const int kk0 = 2 * tig, kk1 = 2 * tig + 1, kk2 = 2 * tig + 8, kk3 = 2 * tig + 9;
    {
        const int ks[4] = {kk0, kk1, kk2, kk3};
        #pragma unroll
        for (int e = 0; e < 4; e++) {
            const int i = ks[e];
            const float sc = bn_g[i] * rsqrtf(bn_v[i] + EPS);
            c0[e] = sc * (pb1[i] - bn_m[i]) + bn_b[i];
        }
    }
    unsigned aw[4];
    aw[0] = packbf(pw2[gr * 16 + kk0], pw2[gr * 16 + kk1]);
    aw[2] = packbf(pw2[gr * 16 + kk2], pw2[gr * 16 + kk3]);
    aw[1] = 0; aw[3] = 0;
    const float pb2g = pb2[gr];
    __syncthreads();

    #pragma unroll 1
    for (int tt = 0; tt < 8; tt++) {
        const int t = warp * 16 + half * 8 + tt;
        const float ct0 = sfeat[t][kk0] + c0[0];
        const float ct1 = sfeat[t][kk1] + c0[1];
        const float ct2 = sfeat[t][kk2] + c0[2];
        const float ct3 = sfeat[t][kk3] + c0[3];
        bf16* orow = Bias + ((long)(gr * NW + n) * T_WIN + t) * T_WIN;

        #pragma unroll
        for (int u0 = 0; u0 < T_WIN; u0 += 8) {
            const int u = u0 + gr;
            const float f0 = fmaxf(ct0 - sfeat[u][kk0], 0.f);
            const float f1 = fmaxf(ct1 - sfeat[u][kk1], 0.f);
            const float f2 = fmaxf(ct2 - sfeat[u][kk2], 0.f);
            const float f3 = fmaxf(ct3 - sfeat[u][kk3], 0.f);
            unsigned bfr[2] = { packbf(f0, f1), packbf(f2, f3) };
            float d[4] = { pb2g, pb2g, 0.f, 0.f };
            mma16816(d, aw, bfr);
            *reinterpret_cast<__nv_bfloat162*>(orow + u0 + 2 * tig) =
                __floats2bfloat162_rn(d[0], d[1]);
        }
    }
}

// ---------------- slim windowed attention ----------------
#define QS_STRIDE 40
#define BS_STRIDE 136

struct AttnSmem {
    bf16 Qs[T_WIN * QS_STRIDE];
    bf16 Ks[T_WIN * QS_STRIDE];
    bf16 Vs[T_WIN * QS_STRIDE];
    bf16 Bs[T_WIN * BS_STRIDE];
};

__global__ __launch_bounds__(256, 2)
void attn_kernel(const bf16* __restrict__ qkv, const bf16* __restrict__ Bias,
                 bf16* __restrict__ O)
{
    extern __shared__ char sraw[];
    AttnSmem& sm = *reinterpret_cast<AttnSmem*>(sraw);

    const int h = blockIdx.x, n = blockIdx.y;
    const int tid = threadIdx.x, lane = tid & 31, warp = tid >> 5;
    const int wr = n >> 4, wc = n & 15;

    const unsigned qb = (unsigned)__cvta_generic_to_shared(sm.Qs);
    const unsigned kb = (unsigned)__cvta_generic_to_shared(sm.Ks);
    const unsigned vb = (unsigned)__cvta_generic_to_shared(sm.Vs);
    const unsigned bb = (unsigned)__cvta_generic_to_shared(sm.Bs);

    {
        const int tok = tid & 127;
        const int l_t = (wr * 4 + (tok >> 5)) * W_IMG + wc * 32 + (tok & 31);
        const bf16* grow = qkv + (long)l_t * QKV_N + h * HD;
        if (tid < 128) {
            #pragma unroll
            for (int c = 0; c < 4; c++)
                cp16(qb + (tok * QS_STRIDE + c * 8) * 2, grow + c * 8);
            cp16(kb + (tok * QS_STRIDE + 0) * 2,  grow + 256);
            cp16(kb + (tok * QS_STRIDE + 8) * 2,  grow + 256 + 8);
        } else {
            cp16(kb + (tok * QS_STRIDE + 16) * 2, grow + 256 + 16);
            cp16(kb + (tok * QS_STRIDE + 24) * 2, grow + 256 + 24);
            #pragma unroll
            for (int c = 0; c < 4; c++)
                cp16(vb + (tok * QS_STRIDE + c * 8) * 2, grow + 512 + c * 8);
        }
        asm volatile("cp.async.commit_group;");
    }

    {
        const int row = tid >> 1, hlf = tid & 1;
        const bf16* brow = Bias + ((long)(h * NW + n) * T_WIN + row) * T_WIN + hlf * 64;
        #pragma unroll
        for (int c = 0; c < 8; c++)
            cp16(bb + (row * BS_STRIDE + hlf * 64 + c * 8) * 2, brow + c * 8);
        asm volatile("cp.async.commit_group;");
    }

    asm volatile("cp.async.wait_group 1;");
    __syncthreads();

    const int mat = lane >> 3, r8 = lane & 7;
    float acc[16][4];
    #pragma unroll
    for (int j = 0; j < 16; j++)
        #pragma unroll
        for (int q = 0; q < 4; q++) acc[j][q] = 0.f;

    #pragma unroll
    for (int ks = 0; ks < 2; ks++) {
        unsigned a[4];
        ldsm4(a, qb + ((warp * 16 + (mat & 1) * 8 + r8) * QS_STRIDE
                       + (mat >> 1) * 8 + ks * 16) * 2);
        #pragma unroll
        for (int nt = 0; nt < 8; nt++) {
            unsigned bfr[4];
            ldsm4(bfr, kb + ((nt * 16 + (mat >> 1) * 8 + r8) * QS_STRIDE
                             + (mat & 1) * 8 + ks * 16) * 2);
            mma16816(acc[2 * nt + 0], a, &bfr[0]);
            mma16816(acc[2 * nt + 1], a, &bfr[2]);
        }
    }

    asm volatile("cp.async.wait_group 0;");
    __syncthreads();

    const int gr = lane >> 2, tig = lane & 3;
    float inv2[2];
    #pragma unroll
    for (int hf = 0; hf < 2; hf++) {
        const int row = warp * 16 + gr + hf * 8;
        float m = -1e30f;
        #pragma unroll
        for (int j = 0; j < 16; j++) {
            const __nv_bfloat162 bb2 = *reinterpret_cast<const __nv_bfloat162*>(
                &sm.Bs[row * BS_STRIDE + j * 8 + tig * 2]);
            const float2 bf = __bfloat1622float2(bb2);
            const float v0 = acc[j][hf * 2 + 0] + bf.x;
            const float v1 = acc[j][hf * 2 + 1] + bf.y;
            acc[j][hf * 2 + 0] = v0;
            acc[j][hf * 2 + 1] = v1;
            m = fmaxf(m, fmaxf(v0, v1));
        }
        m = fmaxf(m, __shfl_xor_sync(0xffffffffu, m, 1));
        m = fmaxf(m, __shfl_xor_sync(0xffffffffu, m, 2));
        float rs = 0.f;
        #pragma unroll
        for (int j = 0; j < 16; j++) {
            const float p0 = __expf(acc[j][hf * 2 + 0] - m);
            const float p1 = __expf(acc[j][hf * 2 + 1] - m);
            acc[j][hf * 2 + 0] = p0;
            acc[j][hf * 2 + 1] = p1;
            rs += p0 + p1;
        }
        rs += __shfl_xor_sync(0xffffffffu, rs, 1);
        rs += __shfl_xor_sync(0xffffffffu, rs, 2);
        inv2[hf] = 1.f / rs;
    }

    float oacc[4][4];
    #pragma unroll
    for (int j = 0; j < 4; j++)
        #pragma unroll
        for (int q = 0; q < 4; q++) oacc[j][q] = 0.f;

    #pragma unroll
    for (int kk = 0; kk < 8; kk++) {
        unsigned ap[4];
        ap[0] = packbf(acc[2 * kk][0],     acc[2 * kk][1]);
        ap[1] = packbf(acc[2 * kk][2],     acc[2 * kk][3]);
        ap[2] = packbf(acc[2 * kk + 1][0], acc[2 * kk + 1][1]);
        ap[3] = packbf(acc[2 * kk + 1][2], acc[2 * kk + 1][3]);
        #pragma unroll
        for (int vt = 0; vt < 2; vt++) {
            unsigned bv4[4];
            ldsm4t(bv4, vb + ((kk * 16 + (mat & 1) * 8 + r8) * QS_STRIDE
                              + (mat >> 1) * 8 + vt * 16) * 2);
            mma16816(oacc[2 * vt + 0], ap, &bv4[0]);
            mma16816(oacc[2 * vt + 1], ap, &bv4[2]);
        }
    }

    #pragma unroll
    for (int hf = 0; hf < 2; hf++) {
        const int row  = warp * 16 + gr + hf * 8;
        const int lrow = (wr * 4 + (row >> 5)) * W_IMG + wc * 32 + (row & 31);
        bf16* orow = O + (long)lrow * C_DIM + h * HD;
        const float sc = inv2[hf];
        #pragma unroll
        for (int j = 0; j < 4; j++) {
            *reinterpret_cast<__nv_bfloat162*>(orow + j * 8 + tig * 2) =
                __floats2bfloat162_rn(oacc[j][hf * 2 + 0] * sc,
                                      oacc[j][hf * 2 + 1] * sc);
        }
    }
}

// ---------------- launch ----------------
extern "C" void kernel_launch(void* const* d_in, const int* in_sizes, int n_in,
                              void* d_out, int out_size)
{
    const float* x      = (const float*)d_in[0];
    const float* pos    = (const float*)d_in[1];
    const float* n1g    = (const float*)d_in[2];
    const float* n1b    = (const float*)d_in[3];
    const float* wq     = (const float*)d_in[4];
    const float* bq     = (const float*)d_in[5];
    const float* wk     = (const float*)d_in[6];
    const float* bk     = (const float*)d_in[7];
    const float* wv     = (const float*)d_in[8];
    const float* bv     = (const float*)d_in[9];
    const float* wo     = (const float*)d_in[10];
    const float* bo     = (const float*)d_in[11];
    const float* n2g    = (const float*)d_in[12];
    const float* n2b    = (const float*)d_in[13];
    const float* wfc1   = (const float*)d_in[14];
    const float* bfc1   = (const float*)d_in[15];
    const float* wfc2   = (const float*)d_in[16];
    const float* bfc2   = (const float*)d_in[17];
    const float* pw1    = (const float*)d_in[18];
    const float* pb1    = (const float*)d_in[19];
    const float* bn_g   = (const float*)d_in[20];
    const float* bn_b   = (const float*)d_in[21];
    const float* bn_m   = (const float*)d_in[22];
    const float* bn_v   = (const float*)d_in[23];
    const float* pw2    = (const float*)d_in[24];
    const float* pb2    = (const float*)d_in[25];
    float* out = (float*)d_out;

    float* base = nullptr;
    cudaGetSymbolAddress((void**)&base, g_scratch);
    bf16*  xn   = (bf16*)(base + 0 * SZ_LC);
    bf16*  qkv  = (bf16*)(base + 1 * SZ_LC);     // slots 1-2
    bf16*  o    = (bf16*)(base + 3 * SZ_LC);
    float* x1   = base + 4 * SZ_LC;
    bf16*  xn2  = (bf16*)(base + 5 * SZ_LC);
    bf16*  hid  = (bf16*)(base + 6 * SZ_LC);     // slots 6-7
    bf16*  Bias = (bf16*)(base + 8 * SZ_LC);     // 64MB tail region

    bf16* wbf = nullptr;
    cudaGetSymbolAddress((void**)&wbf, g_wbf);
    bf16* wqkv_t = wbf + 0;
    bf16* wo_t   = wbf + 196608;
    bf16* fc1_t  = wbf + 262144;
    bf16* fc2_t  = wbf + 524288;
    float* bqkv = nullptr;
    cudaGetSymbolAddress((void**)&bqkv, g_bqkv);

    cudaFuncSetAttribute(mma_gemm<0, true>,  cudaFuncAttributeMaxDynamicSharedMemorySize, GEMM_SMEM);
    cudaFuncSetAttribute(mma_gemm<2, true>,  cudaFuncAttributeMaxDynamicSharedMemorySize, GEMM_SMEM);
    cudaFuncSetAttribute(mma_gemm<1, false>, cudaFuncAttributeMaxDynamicSharedMemorySize, GEMM_SMEM);
    cudaFuncSetAttribute(wo_ln_kernel, cudaFuncAttributeMaxDynamicSharedMemorySize, WOLN_SMEM);
    cudaFuncSetAttribute(attn_kernel, cudaFuncAttributeMaxDynamicSharedMemorySize, (int)sizeof(AttnSmem));

    // 0. pack weights + positional bias tensor
    pack_kernel<<<768, 256>>>(wq, wk, wv, bq, bk, bv, wo, wfc1, wfc2);
    bias_kernel<<<dim3(NW, 2), 256>>>(pos, pw1, pb1, bn_g, bn_b, bn_m, bn_v, pw2, pb2, Bias);

    // 1. xn = LN1(x)
    ln_kernel<<<L_TOK / 8, 256>>>(x, n1g, n1b, xn);

    // 2. qkv = xn @ wqkvT^T + bqkv   (q pre-scaled)
    mma_gemm<0, true><<<dim3(QKV_N / 128, L_TOK / 64), 128, GEMM_SMEM>>>(
        xn, wqkv_t, bqkv, nullptr, qkv, QKV_N, C_DIM);

    // 3. attention
    attn_kernel<<<dim3(NH, NW), 256, sizeof(AttnSmem)>>>(qkv, Bias, o);

    // 4. fused: x1 = x + o @ woT^T + bo ; xn2 = LN2(x1)
    wo_ln_kernel<<<L_TOK / 64, 256, WOLN_SMEM>>>(o, wo_t, bo, x, n2g, n2b, x1, xn2);

    // 5. hid = gelu(xn2 @ fc1T^T + bfc1)
    mma_gemm<2, true><<<dim3(HID_DIM / 128, L_TOK / 64), 128, GEMM_SMEM>>>(
        xn2, fc1_t, bfc1, nullptr, hid, HID_DIM, C_DIM);

    // 6. out = x1 + hid @ fc2T^T + bfc2
    mma_gemm<1, false><<<dim3(C_DIM / 128, L_TOK / 64), 128, GEMM_SMEM>>>(
        hid, fc2_t, bfc2, x1, out, C_DIM, HID_DIM);
}

// round 17
// speedup vs baseline: 1.0146x; 1.0133x over previous
#include <cuda_runtime.h>
#include <cuda_bf16.h>
#include <math.h>

using bf16 = __nv_bfloat16;

// ---------------- problem constants ----------------
#define L_TOK 32768
#define C_DIM 256
#define HID_DIM 1024
#define NW 256
#define NH 8
#define T_WIN 128
#define HD 32
#define W_IMG 512
#define EPS 1e-5f
#define SCALE 0.17677669529663687f
#define QKV_N 768

// ---------------- scratch ----------------
static const size_t SZ_LC = (size_t)L_TOK * C_DIM;
__device__ float g_scratch[8 * 8388608ull + (size_t)L_TOK * HID_DIM];
__device__ bf16  g_wbf[786432];   // wqkvT(196608) | woT(65536) | fc1T(262144) | fc2T(262144)
__device__ float g_bqkv[768];

// ---------------- PTX helpers ----------------
__device__ __forceinline__ void cp16(unsigned saddr, const void* g)
{
    asm volatile("cp.async.cg.shared.global [%0], [%1], 16;" :: "r"(saddr), "l"(g));
}
__device__ __forceinline__ void ldsm4(unsigned* r, unsigned addr)
{
    asm volatile("ldmatrix.sync.aligned.m8n8.x4.shared.b16 {%0,%1,%2,%3}, [%4];"
                 : "=r"(r[0]), "=r"(r[1]), "=r"(r[2]), "=r"(r[3]) : "r"(addr));
}
__device__ __forceinline__ void ldsm4t(unsigned* r, unsigned addr)
{
    asm volatile("ldmatrix.sync.aligned.m8n8.x4.trans.shared.b16 {%0,%1,%2,%3}, [%4];"
                 : "=r"(r[0]), "=r"(r[1]), "=r"(r[2]), "=r"(r[3]) : "r"(addr));
}
__device__ __forceinline__ void mma16816(float* d, const unsigned* a, const unsigned* b)
{
    asm volatile("mma.sync.aligned.m16n8k16.row.col.f32.bf16.bf16.f32 "
                 "{%0,%1,%2,%3}, {%4,%5,%6,%7}, {%8,%9}, {%0,%1,%2,%3};"
                 : "+f"(d[0]), "+f"(d[1]), "+f"(d[2]), "+f"(d[3])
                 : "r"(a[0]), "r"(a[1]), "r"(a[2]), "r"(a[3]), "r"(b[0]), "r"(b[1]));
}
__device__ __forceinline__ unsigned packbf(float a, float b)
{
    __nv_bfloat162 h = __floats2bfloat162_rn(a, b);
    return *reinterpret_cast<unsigned*>(&h);
}

// ---------------- pack: bf16 + transpose weights to [N,K] K-major ----------------
__global__ void pack_kernel(const float* __restrict__ wq, const float* __restrict__ wk,
                            const float* __restrict__ wv, const float* __restrict__ bq,
                            const float* __restrict__ bk, const float* __restrict__ bv,
                            const float* __restrict__ wo, const float* __restrict__ wfc1,
                            const float* __restrict__ wfc2)
{
    const int total = 786432 + 768;
    for (int i = blockIdx.x * blockDim.x + threadIdx.x; i < total; i += gridDim.x * blockDim.x) {
        if (i < 196608) {                         // wqkvT [768][256]
            const int n = i >> 8, k = i & 255;
            float v = (n < 256) ? wq[k * 256 + n] * SCALE
                    : (n < 512) ? wk[k * 256 + n - 256]
                                : wv[k * 256 + n - 512];
            g_wbf[i] = __float2bfloat16(v);
        } else if (i < 262144) {                  // woT [256][256]
            const int j = i - 196608, n = j >> 8, k = j & 255;
            g_wbf[i] = __float2bfloat16(wo[k * 256 + n]);
        } else if (i < 524288) {                  // fc1T [1024][256]
            const int j = i - 262144, n = j >> 8, k = j & 255;
            g_wbf[i] = __float2bfloat16(wfc1[k * 1024 + n]);
        } else if (i < 786432) {                  // fc2T [256][1024]
            const int j = i - 524288, n = j >> 10, k = j & 1023;
            g_wbf[i] = __float2bfloat16(wfc2[k * 256 + n]);
        } else {
            const int c = i - 786432;
            g_bqkv[c] = (c < 256) ? bq[c] * SCALE : (c < 512) ? bk[c - 256] : bv[c - 512];
        }
    }
}

// ---------------- LayerNorm: warp per row, float4x2 per lane ----------------
__global__ __launch_bounds__(256)
void ln_kernel(const float* __restrict__ x,
               const float* __restrict__ g,
               const float* __restrict__ b,
               bf16* __restrict__ y)
{
    const int warp = threadIdx.x >> 5, lane = threadIdx.x & 31;
    const long row = (long)blockIdx.x * 8 + warp;
    const float* xr = x + row * C_DIM + lane * 8;

    const float4 v0 = *reinterpret_cast<const float4*>(xr);
    const float4 v1 = *reinterpret_cast<const float4*>(xr + 4);

    float s  = v0.x + v0.y + v0.z + v0.w + v1.x + v1.y + v1.z + v1.w;
    float sq = v0.x * v0.x + v0.y * v0.y + v0.z * v0.z + v0.w * v0.w
             + v1.x * v1.x + v1.y * v1.y + v1.z * v1.z + v1.w * v1.w;
    #pragma unroll
    for (int o = 16; o > 0; o >>= 1) {
        s  += __shfl_xor_sync(0xffffffffu, s, o);
        sq += __shfl_xor_sync(0xffffffffu, sq, o);
    }
    const float mean = s * (1.f / 256.f);
    const float var  = sq * (1.f / 256.f) - mean * mean;
    const float inv  = rsqrtf(var + EPS);

    const float4 g0 = *reinterpret_cast<const float4*>(g + lane * 8);
    const float4 g1 = *reinterpret_cast<const float4*>(g + lane * 8 + 4);
    const float4 b0 = *reinterpret_cast<const float4*>(b + lane * 8);
    const float4 b1 = *reinterpret_cast<const float4*>(b + lane * 8 + 4);

    uint4 o4;
    o4.x = packbf((v0.x - mean) * inv * g0.x + b0.x, (v0.y - mean) * inv * g0.y + b0.y);
    o4.y = packbf((v0.z - mean) * inv * g0.z + b0.z, (v0.w - mean) * inv * g0.w + b0.w);
    o4.z = packbf((v1.x - mean) * inv * g1.x + b1.x, (v1.y - mean) * inv * g1.y + b1.y);
    o4.w = packbf((v1.z - mean) * inv * g1.z + b1.z, (v1.w - mean) * inv * g1.w + b1.w);
    *reinterpret_cast<uint4*>(y + row * C_DIM + lane * 8) = o4;
}

// ---------------- mma.sync GEMM, 64x128 tile, 128 threads (2x2 warps), 4 CTA/SM ----------------
#define GSTRIDE 72                         // bf16 units per smem row (144B, conflict-free)
#define A_BYTES (64 * GSTRIDE * 2)         // 9216
#define B_BYTES (128 * GSTRIDE * 2)        // 18432
#define STAGE_BYTES (A_BYTES + B_BYTES)    // 27648
#define GEMM_SMEM (2 * STAGE_BYTES + 512)  // 55808

template<int OP, bool BF_OUT>
__global__ __launch_bounds__(128, 4)
void mma_gemm(const bf16* __restrict__ A, const bf16* __restrict__ Bt,
              const float* __restrict__ bias, const float* __restrict__ R,
              void* __restrict__ Cout, int N, int K)
{
    extern __shared__ char smem[];
    const unsigned sb = (unsigned)__cvta_generic_to_shared(smem);
    float* sbias = (float*)(smem + 2 * STAGE_BYTES);

    const int tid  = threadIdx.x;
    const int lane = tid & 31;
    const int wid  = tid >> 5;
    const int wm   = wid >> 1;
    const int wn   = wid & 1;
    const int m0   = blockIdx.y * 64;
    const int n0   = blockIdx.x * 128;

    sbias[tid] = bias[n0 + tid];

    auto issue = [&](int kt, int s) {
        const int kb = kt * 64;
        const unsigned abase = sb + s * STAGE_BYTES;
        const unsigned bbase = abase + A_BYTES;
        #pragma unroll
        for (int p = 0; p < 4; p++) {
            const int id = tid + 128 * p;
            const int r = id >> 3, ch = id & 7;
            cp16(abase + (r * GSTRIDE + ch * 8) * 2, A + (long)(m0 + r) * K + kb + ch * 8);
        }
        #pragma unroll
        for (int p = 0; p < 8; p++) {
            const int id = tid + 128 * p;
            const int r = id >> 3, ch = id & 7;
            cp16(bbase + (r * GSTRIDE + ch * 8) * 2, Bt + (long)(n0 + r) * K + kb + ch * 8);
        }
        asm volatile("cp.async.commit_group;");
    };

    const int mat = lane >> 3, r8 = lane & 7;

    float acc[2][8][4];
    #pragma unroll
    for (int i = 0; i < 2; i++)
        #pragma unroll
        for (int j = 0; j < 8; j++)
            #pragma unroll
            for (int q = 0; q < 4; q++) acc[i][j][q] = 0.f;

    const int KT = K >> 6;
    issue(0, 0);

    for (int kt = 0; kt < KT; kt++) {
        asm volatile("cp.async.wait_group 0;");
        __syncthreads();

        const int s = kt & 1;
        const unsigned abase = sb + s * STAGE_BYTES;
        const unsigned bbase = abase + A_BYTES;

        auto lda = [&](unsigned (*af)[4], int ks) {
            #pragma unroll
            for (int mt = 0; mt < 2; mt++)
                ldsm4(af[mt], abase + ((wm * 32 + mt * 16 + (mat & 1) * 8 + r8) * GSTRIDE
                                       + (mat >> 1) * 8 + ks * 16) * 2);
        };
        auto ldb = [&](unsigned (*bf)[4], int ks) {
            #pragma unroll
            for (int nt = 0; nt < 4; nt++)
                ldsm4(bf[nt], bbase + ((wn * 64 + nt * 16 + (mat >> 1) * 8 + r8) * GSTRIDE
                                       + (mat & 1) * 8 + ks * 16) * 2);
        };

        unsigned af[2][2][4], bf[2][4][4];
        lda(af[0], 0);
        ldb(bf[0], 0);
        if (kt + 1 < KT) issue(kt + 1, s ^ 1);

        #pragma unroll
        for (int ks = 0; ks < 4; ks++) {
            if (ks < 3) {
                lda(af[(ks + 1) & 1], ks + 1);
                ldb(bf[(ks + 1) & 1], ks + 1);
            }
            #pragma unroll
            for (int mt = 0; mt < 2; mt++)
                #pragma unroll
                for (int n8 = 0; n8 < 8; n8++)
                    mma16816(acc[mt][n8], af[ks & 1][mt], &bf[ks & 1][n8 >> 1][(n8 & 1) * 2]);
        }
    }

    const int gr = lane >> 2, tig = lane & 3;
    #pragma unroll
    for (int mt = 0; mt < 2; mt++) {
        #pragma unroll
        for (int n8 = 0; n8 < 8; n8++) {
            const int coll = wn * 64 + n8 * 8 + tig * 2;
            const int col  = n0 + coll;
            const float b0 = sbias[coll], b1 = sbias[coll + 1];
            #pragma unroll
            for (int half = 0; half < 2; half++) {
                const int row = m0 + wm * 32 + mt * 16 + gr + half * 8;
                float v0 = acc[mt][n8][half * 2 + 0] + b0;
                float v1 = acc[mt][n8][half * 2 + 1] + b1;
                if (OP == 1) {
                    const float2 rr = *reinterpret_cast<const float2*>(R + (long)row * N + col);
                    v0 += rr.x; v1 += rr.y;
                }
                if (OP == 2) {
                    v0 = 0.5f * v0 * (1.f + erff(v0 * 0.70710678118654752f));
                    v1 = 0.5f * v1 * (1.f + erff(v1 * 0.70710678118654752f));
                }
                if (BF_OUT) {
                    bf16* C = (bf16*)Cout;
                    *reinterpret_cast<__nv_bfloat162*>(C + (long)row * N + col) =
                        __floats2bfloat162_rn(v0, v1);
                } else {
                    float* C = (float*)Cout;
                    *reinterpret_cast<float2*>(C + (long)row * N + col) = make_float2(v0, v1);
                }
            }
        }
    }
}

// ---------------- fused o-proj + residual + LayerNorm2 (1 sync/chunk pipeline) ----------------
#define WA_BYTES (64 * GSTRIDE * 2)            // 9216
#define WB_BYTES (256 * GSTRIDE * 2)           // 36864
#define WSTAGE (WA_BYTES + WB_BYTES)           // 46080
#define WOLN_SMEM (2 * WSTAGE + 6144)

__global__ __launch_bounds__(256, 2)
void wo_ln_kernel(const bf16* __restrict__ A, const bf16* __restrict__ Bt,
                  const float* __restrict__ bo, const float* __restrict__ x,
                  const float* __restrict__ g2, const float* __restrict__ b2,
                  float* __restrict__ X1, bf16* __restrict__ XN2)
{
    extern __shared__ char smem[];
    const unsigned sb = (unsigned)__cvta_generic_to_shared(smem);
    float* sbo  = (float*)(smem + 2 * WSTAGE);
    float* sg   = sbo + 256;
    float* sb2  = sg + 256;
    float* part = sb2 + 256;     // [64][4]
    float* psq  = part + 256;    // [64][4]
    float* smean = psq + 256;    // [64]
    float* sinv  = smean + 64;   // [64]

    const int tid  = threadIdx.x;
    const int lane = tid & 31;
    const int wid  = tid >> 5;
    const int wm   = wid >> 2;
    const int wn   = wid & 3;
    const int m0   = blockIdx.x * 64;

    sbo[tid] = bo[tid];
    sg[tid]  = g2[tid];
    sb2[tid] = b2[tid];

    auto issue = [&](int kt, int s) {
        const int kb = kt * 64;
        const unsigned abase = sb + s * WSTAGE;
        const unsigned bbase = abase + WA_BYTES;
        #pragma unroll
        for (int p = 0; p < 2; p++) {
            const int id = tid + 256 * p;
            const int r = id >> 3, ch = id & 7;
            cp16(abase + (r * GSTRIDE + ch * 8) * 2, A + (long)(m0 + r) * C_DIM + kb + ch * 8);
        }
        #pragma unroll
        for (int p = 0; p < 8; p++) {
            const int id = tid + 256 * p;
            const int r = id >> 3, ch = id & 7;
            cp16(bbase + (r * GSTRIDE + ch * 8) * 2, Bt + (long)r * C_DIM + kb + ch * 8);
        }
        asm volatile("cp.async.commit_group;");
    };

    const int mat = lane >> 3, r8 = lane & 7;

    float acc[2][8][4];
    #pragma unroll
    for (int i = 0; i < 2; i++)
        #pragma unroll
        for (int j = 0; j < 8; j++)
            #pragma unroll
            for (int q = 0; q < 4; q++) acc[i][j][q] = 0.f;

    issue(0, 0);

    #pragma unroll 1
    for (int kt = 0; kt < 4; kt++) {
        asm volatile("cp.async.wait_group 0;");
        __syncthreads();

        const int s = kt & 1;
        const unsigned abase = sb + s * WSTAGE;
        const unsigned bbase = abase + WA_BYTES;

        auto lda = [&](unsigned (*af)[4], int ks) {
            #pragma unroll
            for (int mt = 0; mt < 2; mt++)
                ldsm4(af[mt], abase + ((wm * 32 + mt * 16 + (mat & 1) * 8 + r8) * GSTRIDE
                                       + (mat >> 1) * 8 + ks * 16) * 2);
        };
        auto ldb = [&](unsigned (*bf)[4], int ks) {
            #pragma unroll
            for (int nt = 0; nt < 4; nt++)
                ldsm4(bf[nt], bbase + ((wn * 64 + nt * 16 + (mat >> 1) * 8 + r8) * GSTRIDE
                                       + (mat & 1) * 8 + ks * 16) * 2);
        };

        unsigned af[2][2][4], bf[2][4][4];
        lda(af[0], 0);
        ldb(bf[0], 0);
        if (kt + 1 < 4) issue(kt + 1, s ^ 1);

        #pragma unroll
        for (int ks = 0; ks < 4; ks++) {
            if (ks < 3) {
                lda(af[(ks + 1) & 1], ks + 1);
                ldb(bf[(ks + 1) & 1], ks + 1);
            }
            #pragma unroll
            for (int mt = 0; mt < 2; mt++)
                #pragma unroll
                for (int n8 = 0; n8 < 8; n8++)
                    mma16816(acc[mt][n8], af[ks & 1][mt], &bf[ks & 1][n8 >> 1][(n8 & 1) * 2]);
        }
    }

    const int gr = lane >> 2, tig = lane & 3;

    #pragma unroll
    for (int mt = 0; mt < 2; mt++) {
        #pragma unroll
        for (int n8 = 0; n8 < 8; n8++) {
            const int col = wn * 64 + n8 * 8 + tig * 2;
            const float c0 = sbo[col], c1 = sbo[col + 1];
            #pragma unroll
            for (int hf = 0; hf < 2; hf++) {
                const long row = m0 + wm * 32 + mt * 16 + gr + hf * 8;
                const float2 rr = *reinterpret_cast<const float2*>(x + row * C_DIM + col);
                acc[mt][n8][hf * 2 + 0] += c0 + rr.x;
                acc[mt][n8][hf * 2 + 1] += c1 + rr.y;
            }
        }
    }

    #pragma unroll
    for (int mt = 0; mt < 2; mt++) {
        #pragma unroll
        for (int hf = 0; hf < 2; hf++) {
            float ls = 0.f, lq = 0.f;
            #pragma unroll
            for (int n8 = 0; n8 < 8; n8++) {
                const float v0 = acc[mt][n8][hf * 2 + 0];
                const float v1 = acc[mt][n8][hf * 2 + 1];
                ls += v0 + v1;
                lq += v0 * v0 + v1 * v1;
            }
            ls += __shfl_xor_sync(0xffffffffu, ls, 1);
            lq += __shfl_xor_sync(0xffffffffu, lq, 1);
            ls += __shfl_xor_sync(0xffffffffu, ls, 2);
            lq += __shfl_xor_sync(0xffffffffu, lq, 2);
            if (tig == 0) {
                const int lr = wm * 32 + mt * 16 + hf * 8 + gr;
                part[lr * 4 + wn] = ls;
                psq[lr * 4 + wn]  = lq;
            }
        }
    }
    __syncthreads();
    if (tid < 64) {
        const float ps = part[tid * 4] + part[tid * 4 + 1] + part[tid * 4 + 2] + part[tid * 4 + 3];
        const float pq = psq[tid * 4]  + psq[tid * 4 + 1]  + psq[tid * 4 + 2]  + psq[tid * 4 + 3];
        const float mean = ps * (1.f / 256.f);
        const float var  = pq * (1.f / 256.f) - mean * mean;
        smean[tid] = mean;
        sinv[tid]  = rsqrtf(var + EPS);
    }
    __syncthreads();

    #pragma unroll
    for (int mt = 0; mt < 2; mt++) {
        #pragma unroll
        for (int hf = 0; hf < 2; hf++) {
            const int lr  = wm * 32 + mt * 16 + hf * 8 + gr;
            const long row = m0 + lr;
            const float mean = smean[lr], inv = sinv[lr];
            #pragma unroll
            for (int n8 = 0; n8 < 8; n8++) {
                const int col = wn * 64 + n8 * 8 + tig * 2;
                const float v0 = acc[mt][n8][hf * 2 + 0];
                const float v1 = acc[mt][n8][hf * 2 + 1];
                *reinterpret_cast<float2*>(X1 + row * C_DIM + col) = make_float2(v0, v1);
                *reinterpret_cast<__nv_bfloat162*>(XN2 + row * C_DIM + col) =
                    __floats2bfloat162_rn((v0 - mean) * inv * sg[col] + sb2[col],
                                          (v1 - mean) * inv * sg[col + 1] + sb2[col + 1]);
            }
        }
    }
}

// ---------------- bias kernel (t-loop split across blockIdx.y) ----------------
__global__ __launch_bounds__(256)
void bias_kernel(const float* __restrict__ pos,
                 const float* __restrict__ pw1, const float* __restrict__ pb1,
                 const float* __restrict__ bn_g, const float* __restrict__ bn_b,
                 const float* __restrict__ bn_m, const float* __restrict__ bn_v,
                 const float* __restrict__ pw2, const float* __restrict__ pb2,
                 bf16* __restrict__ Bias)
{
    __shared__ float sfeat[T_WIN][20];

    const int n    = blockIdx.x;
    const int half = blockIdx.y;
    const int tid  = threadIdx.x;
    const int lane = tid & 31;
    const int warp = tid >> 5;
    const int gr   = lane >> 2;
    const int tig  = lane & 3;
    const int wr   = n >> 4, wc = n & 15;

    if (tid < 128) {
        const int l_t = (wr * 4 + (tid >> 5)) * W_IMG + wc * 32 + (tid & 31);
        const float2 p2 = *reinterpret_cast<const float2*>(pos + (long)l_t * 2);
        #pragma unroll
        for (int i = 0; i < 16; i++) {
            const float sc = bn_g[i] * rsqrtf(bn_v[i] + EPS);
            sfeat[tid][i] = sc * (pw1[2 * i] * p2.x + pw1[2 * i + 1] * p2.y);
        }
    }

    float c0[4];
    const int kk0 = 2 * tig, kk1 = 2 * tig + 1, kk2 = 2 * tig + 8, kk3 = 2 * tig + 9;
    {
        const int ks[4] = {kk0, kk1, kk2, kk3};
        #pragma unroll
        for (int e = 0; e < 4; e++) {
            const int i = ks[e];
            const float sc = bn_g[i] * rsqrtf(bn_v[i] + EPS);
            c0[e] = sc * (pb1[i] - bn_m[i]) + bn_b[i];
        }
    }
    unsigned aw[4];
    aw[0] = packbf(pw2[gr * 16 + kk0], pw2[gr * 16 + kk1]);
    aw[2] = packbf(pw2[gr * 16 + kk2], pw2[gr * 16 + kk3]);
    aw[1] = 0; aw[3] = 0;
    const float pb2g = pb2[gr];
    __syncthreads();

    #pragma unroll 1
    for (int tt = 0; tt < 8; tt++) {
        const int t = warp * 16 + half * 8 + tt;
        const float ct0 = sfeat[t][kk0] + c0[0];
        const float ct1 = sfeat[t][kk1] + c0[1];
        const float ct2 = sfeat[t][kk2] + c0[2];
        const float ct3 = sfeat[t][kk3] + c0[3];
        bf16* orow = Bias + ((long)(gr * NW + n) * T_WIN + t) * T_WIN;

        #pragma unroll
        for (int u0 = 0; u0 < T_WIN; u0 += 8) {
            const int u = u0 + gr;
            const float f0 = fmaxf(ct0 - sfeat[u][kk0], 0.f);
            const float f1 = fmaxf(ct1 - sfeat[u][kk1], 0.f);
            const float f2 = fmaxf(ct2 - sfeat[u][kk2], 0.f);
            const float f3 = fmaxf(ct3 - sfeat[u][kk3], 0.f);
            unsigned bfr[2] = { packbf(f0, f1), packbf(f2, f3) };
            float d[4] = { pb2g, pb2g, 0.f, 0.f };
            mma16816(d, aw, bfr);
            *reinterpret_cast<__nv_bfloat162*>(orow + u0 + 2 * tig) =
                __floats2bfloat162_rn(d[0], d[1]);
        }
    }
}

// ---------------- flash-style windowed attention (two 64-col halves, 3 CTA/SM) ----------------
#define QS_STRIDE 40
#define BS_STRIDE 136

struct AttnSmem {
    bf16 Qs[T_WIN * QS_STRIDE];
    bf16 Ks[T_WIN * QS_STRIDE];
    bf16 Vs[T_WIN * QS_STRIDE];
    bf16 Bs[T_WIN * BS_STRIDE];
};

__global__ __launch_bounds__(256, 3)
void attn_kernel(const bf16* __restrict__ qkv, const bf16* __restrict__ Bias,
                 bf16* __restrict__ O)
{
    extern __shared__ char sraw[];
    AttnSmem& sm = *reinterpret_cast<AttnSmem*>(sraw);

    const int h = blockIdx.x, n = blockIdx.y;
    const int tid = threadIdx.x, lane = tid & 31, warp = tid >> 5;
    const int wr = n >> 4, wc = n & 15;

    const unsigned qb = (unsigned)__cvta_generic_to_shared(sm.Qs);
    const unsigned kb = (unsigned)__cvta_generic_to_shared(sm.Ks);
    const unsigned vb = (unsigned)__cvta_generic_to_shared(sm.Vs);
    const unsigned bb = (unsigned)__cvta_generic_to_shared(sm.Bs);

    {
        const int tok = tid & 127;
        const int l_t = (wr * 4 + (tok >> 5)) * W_IMG + wc * 32 + (tok & 31);
        const bf16* grow = qkv + (long)l_t * QKV_N + h * HD;
        if (tid < 128) {
            #pragma unroll
            for (int c = 0; c < 4; c++)
                cp16(qb + (tok * QS_STRIDE + c * 8) * 2, grow + c * 8);
            cp16(kb + (tok * QS_STRIDE + 0) * 2,  grow + 256);
            cp16(kb + (tok * QS_STRIDE + 8) * 2,  grow + 256 + 8);
        } else {
            cp16(kb + (tok * QS_STRIDE + 16) * 2, grow + 256 + 16);
            cp16(kb + (tok * QS_STRIDE + 24) * 2, grow + 256 + 24);
            #pragma unroll
            for (int c = 0; c < 4; c++)
                cp16(vb + (tok * QS_STRIDE + c * 8) * 2, grow + 512 + c * 8);
        }
        asm volatile("cp.async.commit_group;");
    }

    {
        const int row = tid >> 1, hlf = tid & 1;
        const bf16* brow = Bias + ((long)(h * NW + n) * T_WIN + row) * T_WIN + hlf * 64;
        #pragma unroll
        for (int c = 0; c < 8; c++)
            cp16(bb + (row * BS_STRIDE + hlf * 64 + c * 8) * 2, brow + c * 8);
        asm volatile("cp.async.commit_group;");
    }

    asm volatile("cp.async.wait_group 0;");
    __syncthreads();

    const int mat = lane >> 3, r8 = lane & 7;
    const int gr = lane >> 2, tig = lane & 3;

    // cached Q fragments (reused across both halves)
    unsigned aq[2][4];
    #pragma unroll
    for (int ks = 0; ks < 2; ks++)
        ldsm4(aq[ks], qb + ((warp * 16 + (mat & 1) * 8 + r8) * QS_STRIDE
                            + (mat >> 1) * 8 + ks * 16) * 2);

    float m_[2] = { -1e30f, -1e30f };
    float rs_[2] = { 0.f, 0.f };
    float oacc[4][4];
    #pragma unroll
    for (int j = 0; j < 4; j++)
        #pragma unroll
        for (int q = 0; q < 4; q++) oacc[j][q] = 0.f;

    #pragma unroll
    for (int h2 = 0; h2 < 2; h2++) {
        // S-half = Q @ K[h2*64 .. h2*64+63]^T
        float acc[8][4];
        #pragma unroll
        for (int j = 0; j < 8; j++)
            #pragma unroll
            for (int q = 0; q < 4; q++) acc[j][q] = 0.f;

        #pragma unroll
        for (int ks = 0; ks < 2; ks++) {
            #pragma unroll
            for (int nt = 0; nt < 4; nt++) {
                unsigned bfr[4];
                ldsm4(bfr, kb + ((h2 * 64 + nt * 16 + (mat >> 1) * 8 + r8) * QS_STRIDE
                                 + (mat & 1) * 8 + ks * 16) * 2);
                mma16816(acc[2 * nt + 0], aq[ks], &bfr[0]);
                mma16816(acc[2 * nt + 1], aq[ks], &bfr[2]);
            }
        }

        // bias + online softmax
        #pragma unroll
        for (int hf = 0; hf < 2; hf++) {
            const int row = warp * 16 + gr + hf * 8;
            float mh = -1e30f;
            #pragma unroll
            for (int j = 0; j < 8; j++) {
                const __nv_bfloat162 bb2 = *reinterpret_cast<const __nv_bfloat162*>(
                    &sm.Bs[row * BS_STRIDE + h2 * 64 + j * 8 + tig * 2]);
                const float2 bf = __bfloat1622float2(bb2);
                const float v0 = acc[j][hf * 2 + 0] + bf.x;
                const float v1 = acc[j][hf * 2 + 1] + bf.y;
                acc[j][hf * 2 + 0] = v0;
                acc[j][hf * 2 + 1] = v1;
                mh = fmaxf(mh, fmaxf(v0, v1));
            }
            mh = fmaxf(mh, __shfl_xor_sync(0xffffffffu, mh, 1));
            mh = fmaxf(mh, __shfl_xor_sync(0xffffffffu, mh, 2));
            const float mn = fmaxf(m_[hf], mh);
            const float corr = __expf(m_[hf] - mn);
            rs_[hf] *= corr;
            #pragma unroll
            for (int j = 0; j < 4; j++) {
                oacc[j][hf * 2 + 0] *= corr;
                oacc[j][hf * 2 + 1] *= corr;
            }
            float ls = 0.f;
            #pragma unroll
            for (int j = 0; j < 8; j++) {
                const float p0 = __expf(acc[j][hf * 2 + 0] - mn);
                const float p1 = __expf(acc[j][hf * 2 + 1] - mn);
                acc[j][hf * 2 + 0] = p0;
                acc[j][hf * 2 + 1] = p1;
                ls += p0 + p1;
            }
            rs_[hf] += ls;
            m_[hf] = mn;
        }

        // O += P @ V[h2*64 .. +63]
        #pragma unroll
        for (int kk = 0; kk < 4; kk++) {
            unsigned ap[4];
            ap[0] = packbf(acc[2 * kk][0],     acc[2 * kk][1]);
            ap[1] = packbf(acc[2 * kk][2],     acc[2 * kk][3]);
            ap[2] = packbf(acc[2 * kk + 1][0], acc[2 * kk + 1][1]);
            ap[3] = packbf(acc[2 * kk + 1][2], acc[2 * kk + 1][3]);
            #pragma unroll
            for (int vt = 0; vt < 2; vt++) {
                unsigned bv4[4];
                ldsm4t(bv4, vb + ((h2 * 64 + kk * 16 + (mat & 1) * 8 + r8) * QS_STRIDE
                                  + (mat >> 1) * 8 + vt * 16) * 2);
                mma16816(oacc[2 * vt + 0], ap, &bv4[0]);
                mma16816(oacc[2 * vt + 1], ap, &bv4[2]);
            }
        }
    }

    // finalize: normalize and store
    #pragma unroll
    for (int hf = 0; hf < 2; hf++) {
        float rs = rs_[hf];
        rs += __shfl_xor_sync(0xffffffffu, rs, 1);
        rs += __shfl_xor_sync(0xffffffffu, rs, 2);
        const float sc = 1.f / rs;
        const int row  = warp * 16 + gr + hf * 8;
        const int lrow = (wr * 4 + (row >> 5)) * W_IMG + wc * 32 + (row & 31);
        bf16* orow = O + (long)lrow * C_DIM + h * HD;
        #pragma unroll
        for (int j = 0; j < 4; j++) {
            *reinterpret_cast<__nv_bfloat162*>(orow + j * 8 + tig * 2) =
                __floats2bfloat162_rn(oacc[j][hf * 2 + 0] * sc,
                                      oacc[j][hf * 2 + 1] * sc);
        }
    }
}

// ---------------- launch ----------------
extern "C" void kernel_launch(void* const* d_in, const int* in_sizes, int n_in,
                              void* d_out, int out_size)
{
    const float* x      = (const float*)d_in[0];
    const float* pos    = (const float*)d_in[1];
    const float* n1g    = (const float*)d_in[2];
    const float* n1b    = (const float*)d_in[3];
    const float* wq     = (const float*)d_in[4];
    const float* bq     = (const float*)d_in[5];
    const float* wk     = (const float*)d_in[6];
    const float* bk     = (const float*)d_in[7];
    const float* wv     = (const float*)d_in[8];
    const float* bv     = (const float*)d_in[9];
    const float* wo     = (const float*)d_in[10];
    const float* bo     = (const float*)d_in[11];
    const float* n2g    = (const float*)d_in[12];
    const float* n2b    = (const float*)d_in[13];
    const float* wfc1   = (const float*)d_in[14];
    const float* bfc1   = (const float*)d_in[15];
    const float* wfc2   = (const float*)d_in[16];
    const float* bfc2   = (const float*)d_in[17];
    const float* pw1    = (const float*)d_in[18];
    const float* pb1    = (const float*)d_in[19];
    const float* bn_g   = (const float*)d_in[20];
    const float* bn_b   = (const float*)d_in[21];
    const float* bn_m   = (const float*)d_in[22];
    const float* bn_v   = (const float*)d_in[23];
    const float* pw2    = (const float*)d_in[24];
    const float* pb2    = (const float*)d_in[25];
    float* out = (float*)d_out;

    float* base = nullptr;
    cudaGetSymbolAddress((void**)&base, g_scratch);
    bf16*  xn   = (bf16*)(base + 0 * SZ_LC);
    bf16*  qkv  = (bf16*)(base + 1 * SZ_LC);     // slots 1-2
    bf16*  o    = (bf16*)(base + 3 * SZ_LC);
    float* x1   = base + 4 * SZ_LC;
    bf16*  xn2  = (bf16*)(base + 5 * SZ_LC);
    bf16*  hid  = (bf16*)(base + 6 * SZ_LC);     // slots 6-7
    bf16*  Bias = (bf16*)(base + 8 * SZ_LC);     // 64MB tail region

    bf16* wbf = nullptr;
    cudaGetSymbolAddress((void**)&wbf, g_wbf);
    bf16* wqkv_t = wbf + 0;
    bf16* wo_t   = wbf + 196608;
    bf16* fc1_t  = wbf + 262144;
    bf16* fc2_t  = wbf + 524288;
    float* bqkv = nullptr;
    cudaGetSymbolAddress((void**)&bqkv, g_bqkv);

    cudaFuncSetAttribute(mma_gemm<0, true>,  cudaFuncAttributeMaxDynamicSharedMemorySize, GEMM_SMEM);
    cudaFuncSetAttribute(mma_gemm<2, true>,  cudaFuncAttributeMaxDynamicSharedMemorySize, GEMM_SMEM);
    cudaFuncSetAttribute(mma_gemm<1, false>, cudaFuncAttributeMaxDynamicSharedMemorySize, GEMM_SMEM);
    cudaFuncSetAttribute(wo_ln_kernel, cudaFuncAttributeMaxDynamicSharedMemorySize, WOLN_SMEM);
    cudaFuncSetAttribute(attn_kernel, cudaFuncAttributeMaxDynamicSharedMemorySize, (int)sizeof(AttnSmem));

    // 0. pack weights + positional bias tensor
    pack_kernel<<<768, 256>>>(wq, wk, wv, bq, bk, bv, wo, wfc1, wfc2);
    bias_kernel<<<dim3(NW, 2), 256>>>(pos, pw1, pb1, bn_g, bn_b, bn_m, bn_v, pw2, pb2, Bias);

    // 1. xn = LN1(x)
    ln_kernel<<<L_TOK / 8, 256>>>(x, n1g, n1b, xn);

    // 2. qkv = xn @ wqkvT^T + bqkv   (q pre-scaled)
    mma_gemm<0, true><<<dim3(QKV_N / 128, L_TOK / 64), 128, GEMM_SMEM>>>(
        xn, wqkv_t, bqkv, nullptr, qkv, QKV_N, C_DIM);

    // 3. attention (flash-style, 3 CTA/SM)
    attn_kernel<<<dim3(NH, NW), 256, sizeof(AttnSmem)>>>(qkv, Bias, o);

    // 4. fused: x1 = x + o @ woT^T + bo ; xn2 = LN2(x1)
    wo_ln_kernel<<<L_TOK / 64, 256, WOLN_SMEM>>>(o, wo_t, bo, x, n2g, n2b, x1, xn2);

    // 5. hid = gelu(xn2 @ fc1T^T + bfc1)
    mma_gemm<2, true><<<dim3(HID_DIM / 128, L_TOK / 64), 128, GEMM_SMEM>>>(
        xn2, fc1_t, bfc1, nullptr, hid, HID_DIM, C_DIM);

    // 6. out = x1 + hid @ fc2T^T + bfc2
    mma_gemm<1, false><<<dim3(C_DIM / 128, L_TOK / 64), 128, GEMM_SMEM>>>(
        hid, fc2_t, bfc2, x1, out, C_DIM, HID_DIM);
}